// round 11
// baseline (speedup 1.0000x reference)
#include <cuda_runtime.h>

#define Bdim 256
#define Sdim 512
#define Fdim 64
#define Hdim 128
#define BS   (Bdim * Sdim)
#define NBLK 128           // 2 batch rows per block
#define KQ   28            // streamed Whh quad groups (k = 16..127)
#define NR   14            // register-resident q-groups of the streamed tail

__device__ float g_invDenom[Sdim];
__device__ float g_lossPartial[NBLK];
__device__ float g_WhhQ[KQ * 512 * 4];            // [(q*512+j)*4+r] = Whh[j][16+4q+r]
__device__ float g_gh[(size_t)BS * Hdim];         // gamma_h
__device__ float g_beta[(size_t)BS * Fdim];       // beta
__device__ float g_gml[(size_t)BS * 512];         // [b][s][j]: ml@WihMask^T + bio

typedef unsigned long long u64;
__device__ __forceinline__ u64 pk2(float lo, float hi) {
    u64 r; asm("mov.b64 %0,{%1,%2};" : "=l"(r) : "r"(__float_as_uint(lo)), "r"(__float_as_uint(hi))); return r;
}
__device__ __forceinline__ void up2(u64 v, float& lo, float& hi) {
    unsigned a, b; asm("mov.b64 {%0,%1},%2;" : "=r"(a), "=r"(b) : "l"(v));
    lo = __uint_as_float(a); hi = __uint_as_float(b);
}
__device__ __forceinline__ u64 ff2(u64 a, u64 b, u64 c) {
    u64 d; asm("fma.rn.f32x2 %0,%1,%2,%3;" : "=l"(d) : "l"(a), "l"(b), "l"(c)); return d;
}
__device__ __forceinline__ float sigf(float v) { return 1.f / (1.f + expf(-v)); }

// ================= fused precompute kernel =================
// blockIdx ranges: [0,512) denom | [512,736) whhq | [736,1760) gh
//                  [1760,2784) betak | [2784,4832) gml (j-quarter split)
#define PRE_SMF 9472
#define PRE_SMB (PRE_SMF * 4)   // 37,888 B -> 5-6 CTAs/SM

__global__ __launch_bounds__(256) void rits_pre(
    const float* __restrict__ m,   const float* __restrict__ tt,
    const float* __restrict__ Wdh, const float* __restrict__ bdh,
    const float* __restrict__ Wdm, const float* __restrict__ bdm,
    const float* __restrict__ Wwc, const float* __restrict__ bwc,
    const float* __restrict__ Wih, const float* __restrict__ bih,
    const float* __restrict__ bhh, const float* __restrict__ Whh)
{
    extern __shared__ float sp[];
    const int b = blockIdx.x, t = threadIdx.x;

    if (b < 512) {
        // ---- denom ----
        float* red = sp;
        const int s = b;
        const float4* p = (const float4*)(m + (size_t)t * Sdim * Fdim + (size_t)s * Fdim);
        float sum = 0.f;
#pragma unroll
        for (int i = 0; i < 16; ++i) { float4 v = p[i]; sum += v.x + v.y + v.z + v.w; }
        red[t] = sum;
        __syncthreads();
        for (int off = 128; off > 0; off >>= 1) { if (t < off) red[t] += red[t + off]; __syncthreads(); }
        if (t == 0) g_invDenom[s] = 1.0f / (red[0] + 1e-5f);
    } else if (b < 736) {
        // ---- whhq: Whh streamed-tail swizzle ----
        const int i = (b - 512) * 256 + t;
        if (i < KQ * 512 * 4) {
            const int r = i & 3, j = (i >> 2) & 511, q = i >> 11;
            g_WhhQ[i] = Whh[j * Hdim + 16 + 4 * q + r];
        }
    } else if (b < 1760) {
        // ---- gamma_h ----
        const int blk = b - 736;
        float* w = sp; float* bb = sp + 8192; float* tl = sp + 8320;  // tl[2][128]
        for (int i = t; i < Fdim * Hdim; i += 256) { const int k = i >> 7, h = i & 127; w[i] = Wdh[h * Fdim + k]; }
        if (t < Hdim) bb[t] = bdh[t];
        const int rr = t >> 7, h = t & 127;
        const size_t base = (size_t)blk * 128;
        float v = 0.f;
        if (t < 128) v = tt[(base + (t >> 6)) * Fdim + (t & 63)];
        __syncthreads();
        for (int it = 0; it < 64; ++it) {
            const size_t rs = base + it * 2;
            if (t < 128) tl[(it & 1) * 128 + t] = v;
            __syncthreads();
            if (t < 128 && it < 63) v = tt[(rs + 2 + (t >> 6)) * Fdim + (t & 63)];
            float a0 = 0.f, a1 = 0.f;
            const float* tlr = tl + (it & 1) * 128 + rr * 64;
#pragma unroll 8
            for (int k = 0; k < Fdim; k += 2) { a0 += tlr[k] * w[k * 128 + h]; a1 += tlr[k + 1] * w[(k + 1) * 128 + h]; }
            g_gh[(rs + rr) * Hdim + h] = expf(-fmaxf(a0 + a1 + bb[h], 0.f));
        }
    } else if (b < 2784) {
        // ---- beta ----
        const int blk = b - 1760;
        float* w = sp;                 // 8192
        float* dwdm = sp + 8192; float* cb = sp + 8256; float* cw = sp + 8320;
        float* gm = sp + 8384;         // [2][256]
        float* ms = sp + 8896;         // [2][256]
        for (int i = t; i < 128 * Fdim; i += 256) { const int k = i >> 6, f = i & 63; w[i] = Wwc[f * 128 + k]; }
        if (t < 64) { dwdm[t] = Wdm[t * Fdim + t]; cb[t] = bdm[t]; cw[t] = bwc[t]; }
        const int r = t >> 6, f = t & 63;
        const size_t base = (size_t)blk * 128;
        float vt = tt[(base + r) * Fdim + f], vm = m[(base + r) * Fdim + f];
        __syncthreads();
        for (int it = 0; it < 32; ++it) {
            const size_t rs = base + it * 4 + r;
            const int bf = it & 1;
            gm[bf * 256 + t] = expf(-fmaxf(vt * dwdm[f] + cb[f], 0.f)); ms[bf * 256 + t] = vm;
            __syncthreads();
            if (it < 31) { vt = tt[(rs + 4) * Fdim + f]; vm = m[(rs + 4) * Fdim + f]; }
            float a0 = cw[f], a1 = 0.f;
            const float* gr = gm + bf * 256 + r * 64; const float* mr = ms + bf * 256 + r * 64;
#pragma unroll 8
            for (int k = 0; k < 64; ++k) { a0 += gr[k] * w[k * 64 + f]; a1 += mr[k] * w[(64 + k) * 64 + f]; }
            g_beta[rs * Fdim + f] = a0 + a1;
        }
    } else {
        // ---- gml: natural k-pair packing, j-quarter split, 4 p-rows/iter ----
        const int pb = b - 2784;              // 0..2047
        const int jq = pb & 3, pblk = pb >> 2;  // j-quarter, p-block 0..511
        float* WT  = sp;                      // 8192: [jl<128][kk<64] = Wih[jq*128+jl][64+kk]
        float* BIO = sp + 8192;               // 128
        float* MLP = sp + 8320;               // [2 buf][4 row][2 gq][64 f]
        for (int i = t; i < 8192; i += 256) {
            const int jl = i >> 6, kk = i & 63;
            WT[i] = Wih[(jq * 128 + jl) * 128 + 64 + kk];
        }
        if (t < 128) { const int j = jq * 128 + t; BIO[t] = bih[j] + bhh[j]; }
        const int row = t >> 7, gq = (t >> 6) & 1, f = t & 63;  // staging roles (i=t: row, i=t+256: row+2)
        const int jl = t & 127, ph = t >> 7;                    // compute roles
        const size_t base = (size_t)pblk * 128;
        const size_t bp = base >> 9;                            // constant within block
        float v0, v1;
        {
            const int s0 = (int)(base & 511);
            v0 = m[((2 * bp + gq) * Sdim + s0 + row) * Fdim + f];
            v1 = m[((2 * bp + gq) * Sdim + s0 + row + 2) * Fdim + f];
        }
        __syncthreads();
        const float bj = BIO[jl];
        for (int it = 0; it < 32; ++it) {
            const int s0 = (int)((base + 4 * it) & 511);
            float* B = MLP + (it & 1) * 512;
            B[row * 128 + gq * 64 + f]       = v0;
            B[(row + 2) * 128 + gq * 64 + f] = v1;
            __syncthreads();
            if (it < 31) {
                const int sn0 = (int)((base + 4 * (it + 1)) & 511);
                v0 = m[((2 * bp + gq) * Sdim + sn0 + row) * Fdim + f];
                v1 = m[((2 * bp + gq) * Sdim + sn0 + row + 2) * Fdim + f];
            }
            u64 a00 = 0ULL, a01 = 0ULL, a10 = 0ULL, a11 = 0ULL;
            const float* wrow = WT + jl * 64;
            const float* act = B + (2 * ph) * 128;
#pragma unroll
            for (int kq = 0; kq < 16; ++kq) {
                const ulonglong2 w = *(const ulonglong2*)(wrow + 4 * kq);
                const ulonglong2 x00 = *(const ulonglong2*)(act + 4 * kq);
                const ulonglong2 x01 = *(const ulonglong2*)(act + 64 + 4 * kq);
                const ulonglong2 x10 = *(const ulonglong2*)(act + 128 + 4 * kq);
                const ulonglong2 x11 = *(const ulonglong2*)(act + 192 + 4 * kq);
                a00 = ff2(w.x, x00.x, a00); a00 = ff2(w.y, x00.y, a00);
                a01 = ff2(w.x, x01.x, a01); a01 = ff2(w.y, x01.y, a01);
                a10 = ff2(w.x, x10.x, a10); a10 = ff2(w.y, x10.y, a10);
                a11 = ff2(w.x, x11.x, a11); a11 = ff2(w.y, x11.y, a11);
            }
            const int j = jq * 128 + jl;
            float lo, hi;
            up2(a00, lo, hi);
            g_gml[((2 * bp + 0) * Sdim + s0 + 2 * ph) * 512 + j] = lo + hi + bj;
            up2(a01, lo, hi);
            g_gml[((2 * bp + 1) * Sdim + s0 + 2 * ph) * 512 + j] = lo + hi + bj;
            up2(a10, lo, hi);
            g_gml[((2 * bp + 0) * Sdim + s0 + 2 * ph + 1) * 512 + j] = lo + hi + bj;
            up2(a11, lo, hi);
            g_gml[((2 * bp + 1) * Sdim + s0 + 2 * ph + 1) * 512 + j] = lo + hi + bj;
        }
    }
}

// ================= main sequential kernel (unchanged from R10) =================
#define M_WIHQ 0        // 32768: [q<16][j][4] = Wih[j][4q+r]
#define M_WHHR 32768    // 8192:  [q<4][j][4]  = Whh[j][4q+r]
#define M_WTRQ 40960    // 8192:  [q<32][f][4] = Wtr[f][4q+r]
#define M_WFRQ 49152    // 4096:  [q<16][f][4] = Wfr_m[f][4q+r]
#define M_HR   53248    // 256:  hRow[2][128]
#define M_XC   53504    // 128
#define M_CLC  53632    // 128
#define M_GT   53760    // 1024
#define M_BTR  54784
#define M_BFR  54848
#define M_RED  54912    // 256
#define M_SMF  55168
#define M_SMB  (M_SMF * 4)   // 220,672 B

#define FS2(WP0, WP1, AP, STR) do {                                     \
    const ulonglong2 w0_ = *(const ulonglong2*)(WP0);                   \
    const ulonglong2 w1_ = *(const ulonglong2*)(WP1);                   \
    { const ulonglong2 a_ = *(const ulonglong2*)(AP);                   \
      A00 = ff2(w0_.x, a_.x, A00); A00 = ff2(w0_.y, a_.y, A00);         \
      A10 = ff2(w1_.x, a_.x, A10); A10 = ff2(w1_.y, a_.y, A10); }       \
    { const ulonglong2 a_ = *(const ulonglong2*)((AP) + (STR));         \
      A01 = ff2(w0_.x, a_.x, A01); A01 = ff2(w0_.y, a_.y, A01);         \
      A11 = ff2(w1_.x, a_.x, A11); A11 = ff2(w1_.y, a_.y, A11); }       \
} while (0)

__global__ __launch_bounds__(256, 1) void rits_main(
    const float* __restrict__ x, const float* __restrict__ m,
    const float* __restrict__ Wtr, const float* __restrict__ btr,
    const float* __restrict__ Wfr, const float* __restrict__ bfr,
    const float* __restrict__ Wih, const float* __restrict__ Whh,
    float* __restrict__ out)
{
    extern __shared__ float sm[];
    const int t = threadIdx.x;
    const int b0 = blockIdx.x * 2;

    for (int i = t; i < 32768; i += 256) { const int r = i & 3, j = (i >> 2) & 511, q = i >> 11; sm[M_WIHQ + i] = Wih[j * 128 + 4 * q + r]; }
    for (int i = t; i < 8192; i += 256)  { const int r = i & 3, j = (i >> 2) & 511, q = i >> 11; sm[M_WHHR + i] = Whh[j * 128 + 4 * q + r]; }
    for (int i = t; i < 8192; i += 256)  { const int r = i & 3, f = (i >> 2) & 63, q = i >> 8; sm[M_WTRQ + i] = Wtr[f * 128 + 4 * q + r]; }
    for (int i = t; i < 4096; i += 256)  { const int r = i & 3, f = (i >> 2) & 63, q = i >> 8; const int k = 4 * q + r; sm[M_WFRQ + i] = (k == f) ? 0.f : Wfr[f * 64 + k]; }
    if (t < 64) { sm[M_BTR + t] = btr[t]; sm[M_BFR + t] = bfr[t]; }
    sm[M_HR + t] = 0.f;
    float c_reg = 0.f, loss = 0.f;

    const int rE = t >> 6, fE = t & 63;
    const int j0 = t, j1 = t + 256;
    const int rG = t >> 7, jG = t & 127;

    u64 rw[NR * 4];
#pragma unroll
    for (int q = 0; q < NR; ++q) {
        const ulonglong2 a = *(const ulonglong2*)(g_WhhQ + ((size_t)q * 512 + j0) * 4);
        const ulonglong2 bq = *(const ulonglong2*)(g_WhhQ + ((size_t)q * 512 + j1) * 4);
        rw[4 * q] = a.x; rw[4 * q + 1] = a.y; rw[4 * q + 2] = bq.x; rw[4 * q + 3] = bq.y;
    }

    float cx = 0.f, cm = 0.f, cbeta = 0.f;
    if (t < 128) {
        const size_t idxP = ((size_t)(b0 + rE) * Sdim) * Fdim + fE;
        cx = x[idxP]; cm = m[idxP]; cbeta = g_beta[idxP];
    }
    float cgml[4];
    cgml[0] = g_gml[((size_t)(b0 + 0) * Sdim) * 512 + j0];
    cgml[1] = g_gml[((size_t)(b0 + 1) * Sdim) * 512 + j0];
    cgml[2] = g_gml[((size_t)(b0 + 0) * Sdim) * 512 + j1];
    cgml[3] = g_gml[((size_t)(b0 + 1) * Sdim) * 512 + j1];
    __syncthreads();

    for (int s = 0; s < Sdim; ++s) {
        const int sn = (s < Sdim - 1) ? s + 1 : s;
        const float ghv = g_gh[((size_t)(b0 + rG) * Sdim + sn) * Hdim + jG];
        float nx = 0.f, nm = 0.f, nbeta = 0.f, cInv = 0.f;
        if (t < 128) {
            cInv = g_invDenom[s];
            const size_t idxN = ((size_t)(b0 + rE) * Sdim + sn) * Fdim + fE;
            nx = x[idxN]; nm = m[idxN]; nbeta = g_beta[idxN];
        }
        float ngml[4];
        ngml[0] = g_gml[((size_t)(b0 + 0) * Sdim + sn) * 512 + j0];
        ngml[1] = g_gml[((size_t)(b0 + 1) * Sdim + sn) * 512 + j0];
        ngml[2] = g_gml[((size_t)(b0 + 0) * Sdim + sn) * 512 + j1];
        ngml[3] = g_gml[((size_t)(b0 + 1) * Sdim + sn) * 512 + j1];

        float xh = 0.f;
        if (t < 128) {
            u64 acc = 0ULL;
            const float* hr = sm + M_HR + rE * 128;
#pragma unroll 8
            for (int q = 0; q < 32; ++q) {
                const ulonglong2 w = *(const ulonglong2*)(sm + M_WTRQ + (q * 64 + fE) * 4);
                const ulonglong2 a = *(const ulonglong2*)(hr + 4 * q);
                acc = ff2(w.x, a.x, acc); acc = ff2(w.y, a.y, acc);
            }
            float lo, hi; up2(acc, lo, hi);
            xh = sm[M_BTR + fE] + lo + hi;
            sm[M_XC + rE * 64 + fE] = cm * cx + (1.f - cm) * xh;
        }
        __syncthreads();

        if (t < 128) {
            u64 acc = 0ULL;
            const float* xr = sm + M_XC + rE * 64;
#pragma unroll
            for (int q = 0; q < 16; ++q) {
                const ulonglong2 w = *(const ulonglong2*)(sm + M_WFRQ + (q * 64 + fE) * 4);
                const ulonglong2 a = *(const ulonglong2*)(xr + 4 * q);
                acc = ff2(w.x, a.x, acc); acc = ff2(w.y, a.y, acc);
            }
            float lo, hi; up2(acc, lo, hi);
            const float zh = sm[M_BFR + fE] + lo + hi;
            const float ch = cbeta * zh + (1.f - cbeta) * xh;
            const float cc = cm * cx + (1.f - cm) * ch;
            sm[M_CLC + rE * 64 + fE] = cc;
            out[((size_t)(b0 + rE) * Sdim + s) * Fdim + fE] = cc;
            const float d1 = cx - xh, d2 = cx - zh, d3 = cx - ch;
            loss += cm * (d1 * d1 + d2 * d2 + d3 * d3) * cInv;
        }
        __syncthreads();

        {
            u64 A00 = 0ULL, A01 = 0ULL, A10 = 0ULL, A11 = 0ULL;
#pragma unroll
            for (int q = 0; q < 16; ++q)
                FS2(sm + M_WIHQ + (q * 512 + j0) * 4,
                    sm + M_WIHQ + (q * 512 + j1) * 4,
                    sm + M_CLC + 4 * q, 64);
#pragma unroll
            for (int q = 0; q < 4; ++q)
                FS2(sm + M_WHHR + (q * 512 + j0) * 4,
                    sm + M_WHHR + (q * 512 + j1) * 4,
                    sm + M_HR + 4 * q, 128);
#pragma unroll
            for (int q = 0; q < NR; ++q) {
                const float* AP = sm + M_HR + 16 + 4 * q;
                { const ulonglong2 a_ = *(const ulonglong2*)(AP);
                  A00 = ff2(rw[4 * q], a_.x, A00); A00 = ff2(rw[4 * q + 1], a_.y, A00);
                  A10 = ff2(rw[4 * q + 2], a_.x, A10); A10 = ff2(rw[4 * q + 3], a_.y, A10); }
                { const ulonglong2 a_ = *(const ulonglong2*)(AP + 128);
                  A01 = ff2(rw[4 * q], a_.x, A01); A01 = ff2(rw[4 * q + 1], a_.y, A01);
                  A11 = ff2(rw[4 * q + 2], a_.x, A11); A11 = ff2(rw[4 * q + 3], a_.y, A11); }
            }
#pragma unroll 7
            for (int q = NR; q < KQ; ++q)
                FS2(g_WhhQ + ((size_t)q * 512 + j0) * 4,
                    g_WhhQ + ((size_t)q * 512 + j1) * 4,
                    sm + M_HR + 16 + 4 * q, 128);
            float lo, hi;
            up2(A00, lo, hi); sm[M_GT + 0 * 512 + j0] = lo + hi + cgml[0];
            up2(A01, lo, hi); sm[M_GT + 1 * 512 + j0] = lo + hi + cgml[1];
            up2(A10, lo, hi); sm[M_GT + 0 * 512 + j1] = lo + hi + cgml[2];
            up2(A11, lo, hi); sm[M_GT + 1 * 512 + j1] = lo + hi + cgml[3];
        }
        __syncthreads();

        {
            const float* gg = sm + M_GT + rG * 512;
            const float iv = sigf(gg[jG]);
            const float fv = sigf(gg[128 + jG]);
            const float gv = tanhf(gg[256 + jG]);
            const float ov = sigf(gg[384 + jG]);
            c_reg = fv * c_reg + iv * gv;
            sm[M_HR + rG * 128 + jG] = ov * tanhf(c_reg) * ghv;
        }
        __syncthreads();

        cx = nx; cm = nm; cbeta = nbeta;
#pragma unroll
        for (int r = 0; r < 4; ++r) cgml[r] = ngml[r];
    }

    sm[M_RED + t] = loss;
    __syncthreads();
    for (int off = 128; off > 0; off >>= 1) { if (t < off) sm[M_RED + t] += sm[M_RED + t + off]; __syncthreads(); }
    if (t == 0) g_lossPartial[blockIdx.x] = sm[M_RED];
}

__global__ void rits_loss_final(float* __restrict__ out, int out_size) {
    __shared__ float red[NBLK];
    const int t = threadIdx.x;
    red[t] = g_lossPartial[t];
    __syncthreads();
    for (int off = NBLK / 2; off > 0; off >>= 1) { if (t < off) red[t] += red[t + off]; __syncthreads(); }
    const long long bsf = (long long)Bdim * Sdim * Fdim;
    if (t == 0 && (long long)out_size > bsf) out[bsf] = red[0] / (float)Sdim;
}

extern "C" void kernel_launch(void* const* d_in, const int* in_sizes, int n_in,
                              void* d_out, int out_size) {
    const float* x   = (const float*)d_in[0];
    const float* m   = (const float*)d_in[1];
    const float* tt  = (const float*)d_in[2];
    const float* Wdh = (const float*)d_in[3];
    const float* bdh = (const float*)d_in[4];
    const float* Wdm = (const float*)d_in[5];
    const float* bdm = (const float*)d_in[6];
    const float* Wtr = (const float*)d_in[7];
    const float* btr = (const float*)d_in[8];
    const float* Wfr = (const float*)d_in[9];
    const float* bfr = (const float*)d_in[10];
    const float* Wwc = (const float*)d_in[11];
    const float* bwc = (const float*)d_in[12];
    const float* Wih = (const float*)d_in[13];
    const float* Whh = (const float*)d_in[14];
    const float* bih = (const float*)d_in[15];
    const float* bhh = (const float*)d_in[16];
    float* out = (float*)d_out;

    cudaFuncSetAttribute(rits_pre, cudaFuncAttributeMaxDynamicSharedMemorySize, PRE_SMB);
    cudaFuncSetAttribute(rits_main, cudaFuncAttributeMaxDynamicSharedMemorySize, M_SMB);

    rits_pre<<<4832, 256, PRE_SMB>>>(m, tt, Wdh, bdh, Wdm, bdm, Wwc, bwc, Wih, bih, bhh, Whh);
    rits_main<<<NBLK, 256, M_SMB>>>(x, m, Wtr, btr, Wfr, bfr, Wih, Whh, out);
    rits_loss_final<<<1, NBLK>>>(out, out_size);
}

// round 12
// speedup vs baseline: 1.2890x; 1.2890x over previous
#include <cuda_runtime.h>

#define Bdim 256
#define Sdim 512
#define Fdim 64
#define Hdim 128
#define BS   (Bdim * Sdim)
#define NBLK 128           // 2 batch rows per block
#define KQ   28            // streamed Whh quad groups (k = 16..127)
#define NR   14            // register-resident q-groups of the streamed tail

__device__ float g_invDenom[Sdim];
__device__ float g_lossPartial[NBLK];
__device__ float g_WhhQ[KQ * 512 * 4];            // [(q*512+j)*4+r] = Whh[j][16+4q+r]
__device__ float g_gh[(size_t)BS * Hdim];         // gamma_h
__device__ float g_beta[(size_t)BS * Fdim];       // beta
__device__ float g_gml[(size_t)BS * 512];         // [b][s][j]: ml@WihMask^T + bio

typedef unsigned long long u64;
__device__ __forceinline__ u64 pk2(float lo, float hi) {
    u64 r; asm("mov.b64 %0,{%1,%2};" : "=l"(r) : "r"(__float_as_uint(lo)), "r"(__float_as_uint(hi))); return r;
}
__device__ __forceinline__ void up2(u64 v, float& lo, float& hi) {
    unsigned a, b; asm("mov.b64 {%0,%1},%2;" : "=r"(a), "=r"(b) : "l"(v));
    lo = __uint_as_float(a); hi = __uint_as_float(b);
}
__device__ __forceinline__ u64 ff2(u64 a, u64 b, u64 c) {
    u64 d; asm("fma.rn.f32x2 %0,%1,%2,%3;" : "=l"(d) : "l"(a), "l"(b), "l"(c)); return d;
}
__device__ __forceinline__ float sigf(float v) { return 1.f / (1.f + expf(-v)); }

// ================= fused precompute kernel =================
// blockIdx ranges: [0,512) denom | [512,736) whhq | [736,1760) gh
//                  [1760,2784) betak | [2784,4832) gml (j-quarter split)
#define PRE_SMF 9472
#define PRE_SMB (PRE_SMF * 4)   // 37,888 B -> ~6 CTAs/SM

__global__ __launch_bounds__(256) void rits_pre(
    const float* __restrict__ m,   const float* __restrict__ tt,
    const float* __restrict__ Wdh, const float* __restrict__ bdh,
    const float* __restrict__ Wdm, const float* __restrict__ bdm,
    const float* __restrict__ Wwc, const float* __restrict__ bwc,
    const float* __restrict__ Wih, const float* __restrict__ bih,
    const float* __restrict__ bhh, const float* __restrict__ Whh)
{
    extern __shared__ float sp[];
    const int b = blockIdx.x, t = threadIdx.x;

    if (b < 512) {
        // ---- denom ----
        float* red = sp;
        const int s = b;
        const float4* p = (const float4*)(m + (size_t)t * Sdim * Fdim + (size_t)s * Fdim);
        float sum = 0.f;
#pragma unroll
        for (int i = 0; i < 16; ++i) { float4 v = p[i]; sum += v.x + v.y + v.z + v.w; }
        red[t] = sum;
        __syncthreads();
        for (int off = 128; off > 0; off >>= 1) { if (t < off) red[t] += red[t + off]; __syncthreads(); }
        if (t == 0) g_invDenom[s] = 1.0f / (red[0] + 1e-5f);
    } else if (b < 736) {
        // ---- whhq ----
        const int i = (b - 512) * 256 + t;
        if (i < KQ * 512 * 4) {
            const int r = i & 3, j = (i >> 2) & 511, q = i >> 11;
            g_WhhQ[i] = Whh[j * Hdim + 16 + 4 * q + r];
        }
    } else if (b < 1760) {
        // ---- gamma_h ----
        const int blk = b - 736;
        float* w = sp; float* bb = sp + 8192; float* tl = sp + 8320;  // tl[2][128]
        for (int i = t; i < Fdim * Hdim; i += 256) { const int k = i >> 7, h = i & 127; w[i] = Wdh[h * Fdim + k]; }
        if (t < Hdim) bb[t] = bdh[t];
        const int rr = t >> 7, h = t & 127;
        const size_t base = (size_t)blk * 128;
        float v = 0.f;
        if (t < 128) v = tt[(base + (t >> 6)) * Fdim + (t & 63)];
        __syncthreads();
        for (int it = 0; it < 64; ++it) {
            const size_t rs = base + it * 2;
            if (t < 128) tl[(it & 1) * 128 + t] = v;
            __syncthreads();
            if (t < 128 && it < 63) v = tt[(rs + 2 + (t >> 6)) * Fdim + (t & 63)];
            float a0 = 0.f, a1 = 0.f;
            const float* tlr = tl + (it & 1) * 128 + rr * 64;
#pragma unroll 8
            for (int k = 0; k < Fdim; k += 2) { a0 += tlr[k] * w[k * 128 + h]; a1 += tlr[k + 1] * w[(k + 1) * 128 + h]; }
            g_gh[(rs + rr) * Hdim + h] = expf(-fmaxf(a0 + a1 + bb[h], 0.f));
        }
    } else if (b < 2784) {
        // ---- beta ----
        const int blk = b - 1760;
        float* w = sp;                 // 8192
        float* dwdm = sp + 8192; float* cb = sp + 8256; float* cw = sp + 8320;
        float* gm = sp + 8384;         // [2][256]
        float* ms = sp + 8896;         // [2][256]
        for (int i = t; i < 128 * Fdim; i += 256) { const int k = i >> 6, f = i & 63; w[i] = Wwc[f * 128 + k]; }
        if (t < 64) { dwdm[t] = Wdm[t * Fdim + t]; cb[t] = bdm[t]; cw[t] = bwc[t]; }
        const int r = t >> 6, f = t & 63;
        const size_t base = (size_t)blk * 128;
        float vt = tt[(base + r) * Fdim + f], vm = m[(base + r) * Fdim + f];
        __syncthreads();
        for (int it = 0; it < 32; ++it) {
            const size_t rs = base + it * 4 + r;
            const int bf = it & 1;
            gm[bf * 256 + t] = expf(-fmaxf(vt * dwdm[f] + cb[f], 0.f)); ms[bf * 256 + t] = vm;
            __syncthreads();
            if (it < 31) { vt = tt[(rs + 4) * Fdim + f]; vm = m[(rs + 4) * Fdim + f]; }
            float a0 = cw[f], a1 = 0.f;
            const float* gr = gm + bf * 256 + r * 64; const float* mr = ms + bf * 256 + r * 64;
#pragma unroll 8
            for (int k = 0; k < 64; ++k) { a0 += gr[k] * w[k * 64 + f]; a1 += mr[k] * w[(64 + k) * 64 + f]; }
            g_beta[rs * Fdim + f] = a0 + a1;
        }
    } else {
        // ---- gml: j-quarter split, CONFLICT-FREE j-contiguous weights (R10 pattern) ----
        // WT[(k2*128 + jl)*2 + r] = Wih[(jq*128+jl)*128 + 64 + 2*k2 + r]   (32 KB)
        // thread: jl = t&127 (one j-col), ph = t>>7 (p-pair); 4 p per iter; f32x2 over batch rows
        const int pb = b - 2784;                 // 0..2047
        const int jq = pb & 3, pblk = pb >> 2;   // j-quarter, p-block 0..511
        float* WT  = sp;                         // 8192 floats
        float* BIO = sp + 8192;                  // 128
        float* MLP = sp + 8320;                  // [2 buf][4 row][2f+gq interleave] = 1024
        for (int i = t; i < 8192; i += 256) {
            const int jl = i >> 6, kk = i & 63;  // coalesced global read
            WT[((kk >> 1) * 128 + jl) * 2 + (kk & 1)] = Wih[(jq * 128 + jl) * 128 + 64 + kk];
        }
        if (t < 128) { const int j = jq * 128 + t; BIO[t] = bih[j] + bhh[j]; }
        const int row = t >> 7, gq = (t >> 6) & 1, f = t & 63;  // staging roles
        const int jl = t & 127, ph = t >> 7;                    // compute roles
        const size_t base = (size_t)pblk * 128;
        const size_t bp = base >> 9;             // constant within block
        float v0, v1;
        {
            const int s0 = (int)(base & 511);
            v0 = m[((2 * bp + gq) * Sdim + s0 + row) * Fdim + f];
            v1 = m[((2 * bp + gq) * Sdim + s0 + row + 2) * Fdim + f];
        }
        __syncthreads();
        const float bj = BIO[jl];
        for (int it = 0; it < 32; ++it) {
            const int s0 = (int)((base + 4 * it) & 511);
            float* B = MLP + (it & 1) * 512;
            B[row * 128 + 2 * f + gq]       = v0;
            B[(row + 2) * 128 + 2 * f + gq] = v1;
            __syncthreads();
            if (it < 31) {
                const int sn0 = (int)((base + 4 * (it + 1)) & 511);
                v0 = m[((2 * bp + gq) * Sdim + sn0 + row) * Fdim + f];
                v1 = m[((2 * bp + gq) * Sdim + sn0 + row + 2) * Fdim + f];
            }
            u64 a0 = pk2(bj, bj), a1 = pk2(bj, bj);
            const float* act0 = B + (2 * ph) * 128;
            const float* act1 = B + (2 * ph + 1) * 128;
#pragma unroll 8
            for (int k2 = 0; k2 < 32; ++k2) {
                const float2 w = *(const float2*)(WT + (k2 * 128 + jl) * 2);
                const u64 wx = pk2(w.x, w.x), wy = pk2(w.y, w.y);
                const ulonglong2 q0 = *(const ulonglong2*)(act0 + 4 * k2);
                const ulonglong2 q1 = *(const ulonglong2*)(act1 + 4 * k2);
                a0 = ff2(wx, q0.x, a0); a0 = ff2(wy, q0.y, a0);
                a1 = ff2(wx, q1.x, a1); a1 = ff2(wy, q1.y, a1);
            }
            const int j = jq * 128 + jl;
            float lo, hi;
            up2(a0, lo, hi);
            g_gml[((2 * bp + 0) * Sdim + s0 + 2 * ph) * 512 + j] = lo;
            g_gml[((2 * bp + 1) * Sdim + s0 + 2 * ph) * 512 + j] = hi;
            up2(a1, lo, hi);
            g_gml[((2 * bp + 0) * Sdim + s0 + 2 * ph + 1) * 512 + j] = lo;
            g_gml[((2 * bp + 1) * Sdim + s0 + 2 * ph + 1) * 512 + j] = hi;
        }
    }
}

// ================= main sequential kernel (identical to R10 best) =================
#define M_WIHQ 0        // 32768: [q<16][j][4] = Wih[j][4q+r]
#define M_WHHR 32768    // 8192:  [q<4][j][4]  = Whh[j][4q+r]
#define M_WTRQ 40960    // 8192:  [q<32][f][4] = Wtr[f][4q+r]
#define M_WFRQ 49152    // 4096:  [q<16][f][4] = Wfr_m[f][4q+r]
#define M_HR   53248    // 256:  hRow[2][128]
#define M_XC   53504    // 128
#define M_CLC  53632    // 128
#define M_GT   53760    // 1024
#define M_BTR  54784
#define M_BFR  54848
#define M_RED  54912    // 256
#define M_SMF  55168
#define M_SMB  (M_SMF * 4)   // 220,672 B

#define FS2(WP0, WP1, AP, STR) do {                                     \
    const ulonglong2 w0_ = *(const ulonglong2*)(WP0);                   \
    const ulonglong2 w1_ = *(const ulonglong2*)(WP1);                   \
    { const ulonglong2 a_ = *(const ulonglong2*)(AP);                   \
      A00 = ff2(w0_.x, a_.x, A00); A00 = ff2(w0_.y, a_.y, A00);         \
      A10 = ff2(w1_.x, a_.x, A10); A10 = ff2(w1_.y, a_.y, A10); }       \
    { const ulonglong2 a_ = *(const ulonglong2*)((AP) + (STR));         \
      A01 = ff2(w0_.x, a_.x, A01); A01 = ff2(w0_.y, a_.y, A01);         \
      A11 = ff2(w1_.x, a_.x, A11); A11 = ff2(w1_.y, a_.y, A11); }       \
} while (0)

__global__ __launch_bounds__(256, 1) void rits_main(
    const float* __restrict__ x, const float* __restrict__ m,
    const float* __restrict__ Wtr, const float* __restrict__ btr,
    const float* __restrict__ Wfr, const float* __restrict__ bfr,
    const float* __restrict__ Wih, const float* __restrict__ Whh,
    float* __restrict__ out)
{
    extern __shared__ float sm[];
    const int t = threadIdx.x;
    const int b0 = blockIdx.x * 2;

    for (int i = t; i < 32768; i += 256) { const int r = i & 3, j = (i >> 2) & 511, q = i >> 11; sm[M_WIHQ + i] = Wih[j * 128 + 4 * q + r]; }
    for (int i = t; i < 8192; i += 256)  { const int r = i & 3, j = (i >> 2) & 511, q = i >> 11; sm[M_WHHR + i] = Whh[j * 128 + 4 * q + r]; }
    for (int i = t; i < 8192; i += 256)  { const int r = i & 3, f = (i >> 2) & 63, q = i >> 8; sm[M_WTRQ + i] = Wtr[f * 128 + 4 * q + r]; }
    for (int i = t; i < 4096; i += 256)  { const int r = i & 3, f = (i >> 2) & 63, q = i >> 8; const int k = 4 * q + r; sm[M_WFRQ + i] = (k == f) ? 0.f : Wfr[f * 64 + k]; }
    if (t < 64) { sm[M_BTR + t] = btr[t]; sm[M_BFR + t] = bfr[t]; }
    sm[M_HR + t] = 0.f;
    float c_reg = 0.f, loss = 0.f;

    const int rE = t >> 6, fE = t & 63;
    const int j0 = t, j1 = t + 256;
    const int rG = t >> 7, jG = t & 127;

    u64 rw[NR * 4];
#pragma unroll
    for (int q = 0; q < NR; ++q) {
        const ulonglong2 a = *(const ulonglong2*)(g_WhhQ + ((size_t)q * 512 + j0) * 4);
        const ulonglong2 bq = *(const ulonglong2*)(g_WhhQ + ((size_t)q * 512 + j1) * 4);
        rw[4 * q] = a.x; rw[4 * q + 1] = a.y; rw[4 * q + 2] = bq.x; rw[4 * q + 3] = bq.y;
    }

    float cx = 0.f, cm = 0.f, cbeta = 0.f;
    if (t < 128) {
        const size_t idxP = ((size_t)(b0 + rE) * Sdim) * Fdim + fE;
        cx = x[idxP]; cm = m[idxP]; cbeta = g_beta[idxP];
    }
    float cgml[4];
    cgml[0] = g_gml[((size_t)(b0 + 0) * Sdim) * 512 + j0];
    cgml[1] = g_gml[((size_t)(b0 + 1) * Sdim) * 512 + j0];
    cgml[2] = g_gml[((size_t)(b0 + 0) * Sdim) * 512 + j1];
    cgml[3] = g_gml[((size_t)(b0 + 1) * Sdim) * 512 + j1];
    __syncthreads();

    for (int s = 0; s < Sdim; ++s) {
        const int sn = (s < Sdim - 1) ? s + 1 : s;
        const float ghv = g_gh[((size_t)(b0 + rG) * Sdim + sn) * Hdim + jG];
        float nx = 0.f, nm = 0.f, nbeta = 0.f, cInv = 0.f;
        if (t < 128) {
            cInv = g_invDenom[s];
            const size_t idxN = ((size_t)(b0 + rE) * Sdim + sn) * Fdim + fE;
            nx = x[idxN]; nm = m[idxN]; nbeta = g_beta[idxN];
        }
        float ngml[4];
        ngml[0] = g_gml[((size_t)(b0 + 0) * Sdim + sn) * 512 + j0];
        ngml[1] = g_gml[((size_t)(b0 + 1) * Sdim + sn) * 512 + j0];
        ngml[2] = g_gml[((size_t)(b0 + 0) * Sdim + sn) * 512 + j1];
        ngml[3] = g_gml[((size_t)(b0 + 1) * Sdim + sn) * 512 + j1];

        float xh = 0.f;
        if (t < 128) {
            u64 acc = 0ULL;
            const float* hr = sm + M_HR + rE * 128;
#pragma unroll 8
            for (int q = 0; q < 32; ++q) {
                const ulonglong2 w = *(const ulonglong2*)(sm + M_WTRQ + (q * 64 + fE) * 4);
                const ulonglong2 a = *(const ulonglong2*)(hr + 4 * q);
                acc = ff2(w.x, a.x, acc); acc = ff2(w.y, a.y, acc);
            }
            float lo, hi; up2(acc, lo, hi);
            xh = sm[M_BTR + fE] + lo + hi;
            sm[M_XC + rE * 64 + fE] = cm * cx + (1.f - cm) * xh;
        }
        __syncthreads();

        if (t < 128) {
            u64 acc = 0ULL;
            const float* xr = sm + M_XC + rE * 64;
#pragma unroll
            for (int q = 0; q < 16; ++q) {
                const ulonglong2 w = *(const ulonglong2*)(sm + M_WFRQ + (q * 64 + fE) * 4);
                const ulonglong2 a = *(const ulonglong2*)(xr + 4 * q);
                acc = ff2(w.x, a.x, acc); acc = ff2(w.y, a.y, acc);
            }
            float lo, hi; up2(acc, lo, hi);
            const float zh = sm[M_BFR + fE] + lo + hi;
            const float ch = cbeta * zh + (1.f - cbeta) * xh;
            const float cc = cm * cx + (1.f - cm) * ch;
            sm[M_CLC + rE * 64 + fE] = cc;
            out[((size_t)(b0 + rE) * Sdim + s) * Fdim + fE] = cc;
            const float d1 = cx - xh, d2 = cx - zh, d3 = cx - ch;
            loss += cm * (d1 * d1 + d2 * d2 + d3 * d3) * cInv;
        }
        __syncthreads();

        {
            u64 A00 = 0ULL, A01 = 0ULL, A10 = 0ULL, A11 = 0ULL;
#pragma unroll
            for (int q = 0; q < 16; ++q)
                FS2(sm + M_WIHQ + (q * 512 + j0) * 4,
                    sm + M_WIHQ + (q * 512 + j1) * 4,
                    sm + M_CLC + 4 * q, 64);
#pragma unroll
            for (int q = 0; q < 4; ++q)
                FS2(sm + M_WHHR + (q * 512 + j0) * 4,
                    sm + M_WHHR + (q * 512 + j1) * 4,
                    sm + M_HR + 4 * q, 128);
#pragma unroll
            for (int q = 0; q < NR; ++q) {
                const float* AP = sm + M_HR + 16 + 4 * q;
                { const ulonglong2 a_ = *(const ulonglong2*)(AP);
                  A00 = ff2(rw[4 * q], a_.x, A00); A00 = ff2(rw[4 * q + 1], a_.y, A00);
                  A10 = ff2(rw[4 * q + 2], a_.x, A10); A10 = ff2(rw[4 * q + 3], a_.y, A10); }
                { const ulonglong2 a_ = *(const ulonglong2*)(AP + 128);
                  A01 = ff2(rw[4 * q], a_.x, A01); A01 = ff2(rw[4 * q + 1], a_.y, A01);
                  A11 = ff2(rw[4 * q + 2], a_.x, A11); A11 = ff2(rw[4 * q + 3], a_.y, A11); }
            }
#pragma unroll 7
            for (int q = NR; q < KQ; ++q)
                FS2(g_WhhQ + ((size_t)q * 512 + j0) * 4,
                    g_WhhQ + ((size_t)q * 512 + j1) * 4,
                    sm + M_HR + 16 + 4 * q, 128);
            float lo, hi;
            up2(A00, lo, hi); sm[M_GT + 0 * 512 + j0] = lo + hi + cgml[0];
            up2(A01, lo, hi); sm[M_GT + 1 * 512 + j0] = lo + hi + cgml[1];
            up2(A10, lo, hi); sm[M_GT + 0 * 512 + j1] = lo + hi + cgml[2];
            up2(A11, lo, hi); sm[M_GT + 1 * 512 + j1] = lo + hi + cgml[3];
        }
        __syncthreads();

        {
            const float* gg = sm + M_GT + rG * 512;
            const float iv = sigf(gg[jG]);
            const float fv = sigf(gg[128 + jG]);
            const float gv = tanhf(gg[256 + jG]);
            const float ov = sigf(gg[384 + jG]);
            c_reg = fv * c_reg + iv * gv;
            sm[M_HR + rG * 128 + jG] = ov * tanhf(c_reg) * ghv;
        }
        __syncthreads();

        cx = nx; cm = nm; cbeta = nbeta;
#pragma unroll
        for (int r = 0; r < 4; ++r) cgml[r] = ngml[r];
    }

    sm[M_RED + t] = loss;
    __syncthreads();
    for (int off = 128; off > 0; off >>= 1) { if (t < off) sm[M_RED + t] += sm[M_RED + t + off]; __syncthreads(); }
    if (t == 0) g_lossPartial[blockIdx.x] = sm[M_RED];
}

__global__ void rits_loss_final(float* __restrict__ out, int out_size) {
    __shared__ float red[NBLK];
    const int t = threadIdx.x;
    red[t] = g_lossPartial[t];
    __syncthreads();
    for (int off = NBLK / 2; off > 0; off >>= 1) { if (t < off) red[t] += red[t + off]; __syncthreads(); }
    const long long bsf = (long long)Bdim * Sdim * Fdim;
    if (t == 0 && (long long)out_size > bsf) out[bsf] = red[0] / (float)Sdim;
}

extern "C" void kernel_launch(void* const* d_in, const int* in_sizes, int n_in,
                              void* d_out, int out_size) {
    const float* x   = (const float*)d_in[0];
    const float* m   = (const float*)d_in[1];
    const float* tt  = (const float*)d_in[2];
    const float* Wdh = (const float*)d_in[3];
    const float* bdh = (const float*)d_in[4];
    const float* Wdm = (const float*)d_in[5];
    const float* bdm = (const float*)d_in[6];
    const float* Wtr = (const float*)d_in[7];
    const float* btr = (const float*)d_in[8];
    const float* Wfr = (const float*)d_in[9];
    const float* bfr = (const float*)d_in[10];
    const float* Wwc = (const float*)d_in[11];
    const float* bwc = (const float*)d_in[12];
    const float* Wih = (const float*)d_in[13];
    const float* Whh = (const float*)d_in[14];
    const float* bih = (const float*)d_in[15];
    const float* bhh = (const float*)d_in[16];
    float* out = (float*)d_out;

    cudaFuncSetAttribute(rits_pre, cudaFuncAttributeMaxDynamicSharedMemorySize, PRE_SMB);
    cudaFuncSetAttribute(rits_main, cudaFuncAttributeMaxDynamicSharedMemorySize, M_SMB);

    rits_pre<<<4832, 256, PRE_SMB>>>(m, tt, Wdh, bdh, Wdm, bdm, Wwc, bwc, Wih, bih, bhh, Whh);
    rits_main<<<NBLK, 256, M_SMB>>>(x, m, Wtr, btr, Wfr, bfr, Wih, Whh, out);
    rits_loss_final<<<1, NBLK>>>(out, out_size);
}

// round 13
// speedup vs baseline: 1.3407x; 1.0401x over previous
#include <cuda_runtime.h>

#define Bdim 256
#define Sdim 512
#define Fdim 64
#define Hdim 128
#define BS   (Bdim * Sdim)
#define NBLK 128           // 2 batch rows per block
#define KQ   28            // streamed Whh quad groups (k = 16..127)
#define NR   14            // register-resident q-groups of the streamed tail

__device__ float g_invDenom[Sdim];
__device__ float g_lossPartial[NBLK];
__device__ float g_WhhQ[KQ * 512 * 4];            // [(q*512+j)*4+r] = Whh[j][16+4q+r]
__device__ float g_gh[(size_t)BS * Hdim];         // gamma_h
__device__ float g_beta[(size_t)BS * Fdim];       // beta
__device__ float g_gml[(size_t)BS * 512];         // [b][s][j]: ml@WihMask^T + bio

typedef unsigned long long u64;
__device__ __forceinline__ u64 pk2(float lo, float hi) {
    u64 r; asm("mov.b64 %0,{%1,%2};" : "=l"(r) : "r"(__float_as_uint(lo)), "r"(__float_as_uint(hi))); return r;
}
__device__ __forceinline__ void up2(u64 v, float& lo, float& hi) {
    unsigned a, b; asm("mov.b64 {%0,%1},%2;" : "=r"(a), "=r"(b) : "l"(v));
    lo = __uint_as_float(a); hi = __uint_as_float(b);
}
__device__ __forceinline__ u64 ff2(u64 a, u64 b, u64 c) {
    u64 d; asm("fma.rn.f32x2 %0,%1,%2,%3;" : "=l"(d) : "l"(a), "l"(b), "l"(c)); return d;
}
__device__ __forceinline__ float sigf(float v) { return 1.0f / (1.0f + expf(-v)); }
// fast gate math (main G phase only): __expf rel-err 2^-21
__device__ __forceinline__ float fsig(float v) {
    const float e = __expf(-v);
    return __fdividef(1.0f, 1.0f + e);
}
__device__ __forceinline__ float ftanh(float v) {
    const float vc = fminf(fmaxf(v, -15.0f), 15.0f);
    const float e = __expf(2.0f * vc);
    return __fdividef(e - 1.0f, e + 1.0f);
}

// ================= fused precompute kernel (identical to R12) =================
// blockIdx ranges: [0,512) denom | [512,736) whhq | [736,1760) gh
//                  [1760,2784) betak | [2784,4832) gml (j-quarter split)
#define PRE_SMF 9472
#define PRE_SMB (PRE_SMF * 4)   // 37,888 B

__global__ __launch_bounds__(256) void rits_pre(
    const float* __restrict__ m,   const float* __restrict__ tt,
    const float* __restrict__ Wdh, const float* __restrict__ bdh,
    const float* __restrict__ Wdm, const float* __restrict__ bdm,
    const float* __restrict__ Wwc, const float* __restrict__ bwc,
    const float* __restrict__ Wih, const float* __restrict__ bih,
    const float* __restrict__ bhh, const float* __restrict__ Whh)
{
    extern __shared__ float sp[];
    const int b = blockIdx.x, t = threadIdx.x;

    if (b < 512) {
        // ---- denom ----
        float* red = sp;
        const int s = b;
        const float4* p = (const float4*)(m + (size_t)t * Sdim * Fdim + (size_t)s * Fdim);
        float sum = 0.f;
#pragma unroll
        for (int i = 0; i < 16; ++i) { float4 v = p[i]; sum += v.x + v.y + v.z + v.w; }
        red[t] = sum;
        __syncthreads();
        for (int off = 128; off > 0; off >>= 1) { if (t < off) red[t] += red[t + off]; __syncthreads(); }
        if (t == 0) g_invDenom[s] = 1.0f / (red[0] + 1e-5f);
    } else if (b < 736) {
        // ---- whhq ----
        const int i = (b - 512) * 256 + t;
        if (i < KQ * 512 * 4) {
            const int r = i & 3, j = (i >> 2) & 511, q = i >> 11;
            g_WhhQ[i] = Whh[j * Hdim + 16 + 4 * q + r];
        }
    } else if (b < 1760) {
        // ---- gamma_h ----
        const int blk = b - 736;
        float* w = sp; float* bb = sp + 8192; float* tl = sp + 8320;  // tl[2][128]
        for (int i = t; i < Fdim * Hdim; i += 256) { const int k = i >> 7, h = i & 127; w[i] = Wdh[h * Fdim + k]; }
        if (t < Hdim) bb[t] = bdh[t];
        const int rr = t >> 7, h = t & 127;
        const size_t base = (size_t)blk * 128;
        float v = 0.f;
        if (t < 128) v = tt[(base + (t >> 6)) * Fdim + (t & 63)];
        __syncthreads();
        for (int it = 0; it < 64; ++it) {
            const size_t rs = base + it * 2;
            if (t < 128) tl[(it & 1) * 128 + t] = v;
            __syncthreads();
            if (t < 128 && it < 63) v = tt[(rs + 2 + (t >> 6)) * Fdim + (t & 63)];
            float a0 = 0.f, a1 = 0.f;
            const float* tlr = tl + (it & 1) * 128 + rr * 64;
#pragma unroll 8
            for (int k = 0; k < Fdim; k += 2) { a0 += tlr[k] * w[k * 128 + h]; a1 += tlr[k + 1] * w[(k + 1) * 128 + h]; }
            g_gh[(rs + rr) * Hdim + h] = expf(-fmaxf(a0 + a1 + bb[h], 0.f));
        }
    } else if (b < 2784) {
        // ---- beta ----
        const int blk = b - 1760;
        float* w = sp;
        float* dwdm = sp + 8192; float* cb = sp + 8256; float* cw = sp + 8320;
        float* gm = sp + 8384;         // [2][256]
        float* ms = sp + 8896;         // [2][256]
        for (int i = t; i < 128 * Fdim; i += 256) { const int k = i >> 6, f = i & 63; w[i] = Wwc[f * 128 + k]; }
        if (t < 64) { dwdm[t] = Wdm[t * Fdim + t]; cb[t] = bdm[t]; cw[t] = bwc[t]; }
        const int r = t >> 6, f = t & 63;
        const size_t base = (size_t)blk * 128;
        float vt = tt[(base + r) * Fdim + f], vm = m[(base + r) * Fdim + f];
        __syncthreads();
        for (int it = 0; it < 32; ++it) {
            const size_t rs = base + it * 4 + r;
            const int bf = it & 1;
            gm[bf * 256 + t] = expf(-fmaxf(vt * dwdm[f] + cb[f], 0.f)); ms[bf * 256 + t] = vm;
            __syncthreads();
            if (it < 31) { vt = tt[(rs + 4) * Fdim + f]; vm = m[(rs + 4) * Fdim + f]; }
            float a0 = cw[f], a1 = 0.f;
            const float* gr = gm + bf * 256 + r * 64; const float* mr = ms + bf * 256 + r * 64;
#pragma unroll 8
            for (int k = 0; k < 64; ++k) { a0 += gr[k] * w[k * 64 + f]; a1 += mr[k] * w[(64 + k) * 64 + f]; }
            g_beta[rs * Fdim + f] = a0 + a1;
        }
    } else {
        // ---- gml: j-quarter split, conflict-free j-contiguous weights ----
        const int pb = b - 2784;
        const int jq = pb & 3, pblk = pb >> 2;
        float* WT  = sp;                         // 8192 floats
        float* BIO = sp + 8192;                  // 128
        float* MLP = sp + 8320;                  // [2][4][128]
        for (int i = t; i < 8192; i += 256) {
            const int jl = i >> 6, kk = i & 63;
            WT[((kk >> 1) * 128 + jl) * 2 + (kk & 1)] = Wih[(jq * 128 + jl) * 128 + 64 + kk];
        }
        if (t < 128) { const int j = jq * 128 + t; BIO[t] = bih[j] + bhh[j]; }
        const int row = t >> 7, gq = (t >> 6) & 1, f = t & 63;
        const int jl = t & 127, ph = t >> 7;
        const size_t base = (size_t)pblk * 128;
        const size_t bp = base >> 9;
        float v0, v1;
        {
            const int s0 = (int)(base & 511);
            v0 = m[((2 * bp + gq) * Sdim + s0 + row) * Fdim + f];
            v1 = m[((2 * bp + gq) * Sdim + s0 + row + 2) * Fdim + f];
        }
        __syncthreads();
        const float bj = BIO[jl];
        for (int it = 0; it < 32; ++it) {
            const int s0 = (int)((base + 4 * it) & 511);
            float* B = MLP + (it & 1) * 512;
            B[row * 128 + 2 * f + gq]       = v0;
            B[(row + 2) * 128 + 2 * f + gq] = v1;
            __syncthreads();
            if (it < 31) {
                const int sn0 = (int)((base + 4 * (it + 1)) & 511);
                v0 = m[((2 * bp + gq) * Sdim + sn0 + row) * Fdim + f];
                v1 = m[((2 * bp + gq) * Sdim + sn0 + row + 2) * Fdim + f];
            }
            u64 a0 = pk2(bj, bj), a1 = pk2(bj, bj);
            const float* act0 = B + (2 * ph) * 128;
            const float* act1 = B + (2 * ph + 1) * 128;
#pragma unroll 8
            for (int k2 = 0; k2 < 32; ++k2) {
                const float2 w = *(const float2*)(WT + (k2 * 128 + jl) * 2);
                const u64 wx = pk2(w.x, w.x), wy = pk2(w.y, w.y);
                const ulonglong2 q0 = *(const ulonglong2*)(act0 + 4 * k2);
                const ulonglong2 q1 = *(const ulonglong2*)(act1 + 4 * k2);
                a0 = ff2(wx, q0.x, a0); a0 = ff2(wy, q0.y, a0);
                a1 = ff2(wx, q1.x, a1); a1 = ff2(wy, q1.y, a1);
            }
            const int j = jq * 128 + jl;
            float lo, hi;
            up2(a0, lo, hi);
            g_gml[((2 * bp + 0) * Sdim + s0 + 2 * ph) * 512 + j] = lo;
            g_gml[((2 * bp + 1) * Sdim + s0 + 2 * ph) * 512 + j] = hi;
            up2(a1, lo, hi);
            g_gml[((2 * bp + 0) * Sdim + s0 + 2 * ph + 1) * 512 + j] = lo;
            g_gml[((2 * bp + 1) * Sdim + s0 + 2 * ph + 1) * 512 + j] = hi;
        }
    }
}

// ================= main sequential kernel =================
#define M_WIHQ 0        // 32768: [q<16][j][4] = Wih[j][4q+r]
#define M_WHHR 32768    // 8192:  [q<4][j][4]  = Whh[j][4q+r]
#define M_WTRQ 40960    // 8192:  [q<32][f][4] = Wtr[f][4q+r]
#define M_WFRQ 49152    // 4096:  [q<16][f][4] = Wfr_m[f][4q+r]
#define M_HR   53248    // 256:  hRow[2][128]
#define M_XC   53504    // 128
#define M_CLC  53632    // 128
#define M_GT   53760    // 1024
#define M_BTR  54784
#define M_BFR  54848
#define M_RED  54912    // 256
#define M_SMF  55168
#define M_SMB  (M_SMF * 4)   // 220,672 B

#define FS2(WP0, WP1, AP, STR) do {                                     \
    const ulonglong2 w0_ = *(const ulonglong2*)(WP0);                   \
    const ulonglong2 w1_ = *(const ulonglong2*)(WP1);                   \
    { const ulonglong2 a_ = *(const ulonglong2*)(AP);                   \
      A00 = ff2(w0_.x, a_.x, A00); A00 = ff2(w0_.y, a_.y, A00);         \
      A10 = ff2(w1_.x, a_.x, A10); A10 = ff2(w1_.y, a_.y, A10); }       \
    { const ulonglong2 a_ = *(const ulonglong2*)((AP) + (STR));         \
      A01 = ff2(w0_.x, a_.x, A01); A01 = ff2(w0_.y, a_.y, A01);         \
      A11 = ff2(w1_.x, a_.x, A11); A11 = ff2(w1_.y, a_.y, A11); }       \
} while (0)

__global__ __launch_bounds__(256, 1) void rits_main(
    const float* __restrict__ x, const float* __restrict__ m,
    const float* __restrict__ Wtr, const float* __restrict__ btr,
    const float* __restrict__ Wfr, const float* __restrict__ bfr,
    const float* __restrict__ Wih, const float* __restrict__ Whh,
    float* __restrict__ out)
{
    extern __shared__ float sm[];
    const int t = threadIdx.x;
    const int b0 = blockIdx.x * 2;

    for (int i = t; i < 32768; i += 256) { const int r = i & 3, j = (i >> 2) & 511, q = i >> 11; sm[M_WIHQ + i] = Wih[j * 128 + 4 * q + r]; }
    for (int i = t; i < 8192; i += 256)  { const int r = i & 3, j = (i >> 2) & 511, q = i >> 11; sm[M_WHHR + i] = Whh[j * 128 + 4 * q + r]; }
    for (int i = t; i < 8192; i += 256)  { const int r = i & 3, f = (i >> 2) & 63, q = i >> 8; sm[M_WTRQ + i] = Wtr[f * 128 + 4 * q + r]; }
    for (int i = t; i < 4096; i += 256)  { const int r = i & 3, f = (i >> 2) & 63, q = i >> 8; const int k = 4 * q + r; sm[M_WFRQ + i] = (k == f) ? 0.f : Wfr[f * 64 + k]; }
    if (t < 64) { sm[M_BTR + t] = btr[t]; sm[M_BFR + t] = bfr[t]; }
    sm[M_HR + t] = 0.f;
    float c_reg = 0.f, loss = 0.f;

    const int rE = t >> 6, fE = t & 63;
    const int j0 = t, j1 = t + 256;
    const int rG = t >> 7, jG = t & 127;

    u64 rw[NR * 4];
#pragma unroll
    for (int q = 0; q < NR; ++q) {
        const ulonglong2 a = *(const ulonglong2*)(g_WhhQ + ((size_t)q * 512 + j0) * 4);
        const ulonglong2 bq = *(const ulonglong2*)(g_WhhQ + ((size_t)q * 512 + j1) * 4);
        rw[4 * q] = a.x; rw[4 * q + 1] = a.y; rw[4 * q + 2] = bq.x; rw[4 * q + 3] = bq.y;
    }

    float cx = 0.f, cm = 0.f, cbeta = 0.f;
    if (t < 128) {
        const size_t idxP = ((size_t)(b0 + rE) * Sdim) * Fdim + fE;
        cx = x[idxP]; cm = m[idxP]; cbeta = g_beta[idxP];
    }
    float cgml[4];
    cgml[0] = g_gml[((size_t)(b0 + 0) * Sdim) * 512 + j0];
    cgml[1] = g_gml[((size_t)(b0 + 1) * Sdim) * 512 + j0];
    cgml[2] = g_gml[((size_t)(b0 + 0) * Sdim) * 512 + j1];
    cgml[3] = g_gml[((size_t)(b0 + 1) * Sdim) * 512 + j1];
    __syncthreads();

    for (int s = 0; s < Sdim; ++s) {
        const int sn = (s < Sdim - 1) ? s + 1 : s;
        const float ghv = g_gh[((size_t)(b0 + rG) * Sdim + sn) * Hdim + jG];
        float nx = 0.f, nm = 0.f, nbeta = 0.f, cInv = 0.f;
        if (t < 128) {
            cInv = g_invDenom[s];
            const size_t idxN = ((size_t)(b0 + rE) * Sdim + sn) * Fdim + fE;
            nx = x[idxN]; nm = m[idxN]; nbeta = g_beta[idxN];
        }
        float ngml[4];
        ngml[0] = g_gml[((size_t)(b0 + 0) * Sdim + sn) * 512 + j0];
        ngml[1] = g_gml[((size_t)(b0 + 1) * Sdim + sn) * 512 + j0];
        ngml[2] = g_gml[((size_t)(b0 + 0) * Sdim + sn) * 512 + j1];
        ngml[3] = g_gml[((size_t)(b0 + 1) * Sdim + sn) * 512 + j1];

        // C: xl_hat = h @ Wtr^T + btr (4 independent chains) ; xl_c
        float xh = 0.f;
        if (t < 128) {
            u64 ac0 = 0ULL, ac1 = 0ULL, ac2 = 0ULL, ac3 = 0ULL;
            const float* hr = sm + M_HR + rE * 128;
#pragma unroll
            for (int q = 0; q < 32; q += 4) {
                { const ulonglong2 w = *(const ulonglong2*)(sm + M_WTRQ + (q * 64 + fE) * 4);
                  const ulonglong2 a = *(const ulonglong2*)(hr + 4 * q);
                  ac0 = ff2(w.x, a.x, ac0); ac0 = ff2(w.y, a.y, ac0); }
                { const ulonglong2 w = *(const ulonglong2*)(sm + M_WTRQ + ((q + 1) * 64 + fE) * 4);
                  const ulonglong2 a = *(const ulonglong2*)(hr + 4 * (q + 1));
                  ac1 = ff2(w.x, a.x, ac1); ac1 = ff2(w.y, a.y, ac1); }
                { const ulonglong2 w = *(const ulonglong2*)(sm + M_WTRQ + ((q + 2) * 64 + fE) * 4);
                  const ulonglong2 a = *(const ulonglong2*)(hr + 4 * (q + 2));
                  ac2 = ff2(w.x, a.x, ac2); ac2 = ff2(w.y, a.y, ac2); }
                { const ulonglong2 w = *(const ulonglong2*)(sm + M_WTRQ + ((q + 3) * 64 + fE) * 4);
                  const ulonglong2 a = *(const ulonglong2*)(hr + 4 * (q + 3));
                  ac3 = ff2(w.x, a.x, ac3); ac3 = ff2(w.y, a.y, ac3); }
            }
            float l0, h0, l1, h1, l2, h2, l3, h3;
            up2(ac0, l0, h0); up2(ac1, l1, h1); up2(ac2, l2, h2); up2(ac3, l3, h3);
            xh = sm[M_BTR + fE] + ((l0 + h0) + (l1 + h1)) + ((l2 + h2) + (l3 + h3));
            sm[M_XC + rE * 64 + fE] = cm * cx + (1.f - cm) * xh;
        }
        __syncthreads();

        // D+E: zl_hat (2 chains), cl_hat, cl_c, output, loss
        if (t < 128) {
            u64 ac0 = 0ULL, ac1 = 0ULL;
            const float* xr = sm + M_XC + rE * 64;
#pragma unroll
            for (int q = 0; q < 16; q += 2) {
                { const ulonglong2 w = *(const ulonglong2*)(sm + M_WFRQ + (q * 64 + fE) * 4);
                  const ulonglong2 a = *(const ulonglong2*)(xr + 4 * q);
                  ac0 = ff2(w.x, a.x, ac0); ac0 = ff2(w.y, a.y, ac0); }
                { const ulonglong2 w = *(const ulonglong2*)(sm + M_WFRQ + ((q + 1) * 64 + fE) * 4);
                  const ulonglong2 a = *(const ulonglong2*)(xr + 4 * (q + 1));
                  ac1 = ff2(w.x, a.x, ac1); ac1 = ff2(w.y, a.y, ac1); }
            }
            float l0, h0, l1, h1;
            up2(ac0, l0, h0); up2(ac1, l1, h1);
            const float zh = sm[M_BFR + fE] + (l0 + h0) + (l1 + h1);
            const float ch = cbeta * zh + (1.f - cbeta) * xh;
            const float cc = cm * cx + (1.f - cm) * ch;
            sm[M_CLC + rE * 64 + fE] = cc;
            out[((size_t)(b0 + rE) * Sdim + s) * Fdim + fE] = cc;
            const float d1 = cx - xh, d2 = cx - zh, d3 = cx - ch;
            loss += cm * (d1 * d1 + d2 * d2 + d3 * d3) * cInv;
        }
        __syncthreads();

        // F: gates = gml + clc @ WihClc^T + h @ Whh^T
        {
            u64 A00 = 0ULL, A01 = 0ULL, A10 = 0ULL, A11 = 0ULL;
#pragma unroll
            for (int q = 0; q < 16; ++q)
                FS2(sm + M_WIHQ + (q * 512 + j0) * 4,
                    sm + M_WIHQ + (q * 512 + j1) * 4,
                    sm + M_CLC + 4 * q, 64);
#pragma unroll
            for (int q = 0; q < 4; ++q)
                FS2(sm + M_WHHR + (q * 512 + j0) * 4,
                    sm + M_WHHR + (q * 512 + j1) * 4,
                    sm + M_HR + 4 * q, 128);
#pragma unroll
            for (int q = 0; q < NR; ++q) {
                const float* AP = sm + M_HR + 16 + 4 * q;
                { const ulonglong2 a_ = *(const ulonglong2*)(AP);
                  A00 = ff2(rw[4 * q], a_.x, A00); A00 = ff2(rw[4 * q + 1], a_.y, A00);
                  A10 = ff2(rw[4 * q + 2], a_.x, A10); A10 = ff2(rw[4 * q + 3], a_.y, A10); }
                { const ulonglong2 a_ = *(const ulonglong2*)(AP + 128);
                  A01 = ff2(rw[4 * q], a_.x, A01); A01 = ff2(rw[4 * q + 1], a_.y, A01);
                  A11 = ff2(rw[4 * q + 2], a_.x, A11); A11 = ff2(rw[4 * q + 3], a_.y, A11); }
            }
#pragma unroll 7
            for (int q = NR; q < KQ; ++q)
                FS2(g_WhhQ + ((size_t)q * 512 + j0) * 4,
                    g_WhhQ + ((size_t)q * 512 + j1) * 4,
                    sm + M_HR + 16 + 4 * q, 128);
            float lo, hi;
            up2(A00, lo, hi); sm[M_GT + 0 * 512 + j0] = lo + hi + cgml[0];
            up2(A01, lo, hi); sm[M_GT + 1 * 512 + j0] = lo + hi + cgml[1];
            up2(A10, lo, hi); sm[M_GT + 0 * 512 + j1] = lo + hi + cgml[2];
            up2(A11, lo, hi); sm[M_GT + 1 * 512 + j1] = lo + hi + cgml[3];
        }
        __syncthreads();

        // G: LSTM update + apply gamma_h(s+1)  (fast transcendentals)
        {
            const float* gg = sm + M_GT + rG * 512;
            const float iv = fsig(gg[jG]);
            const float fv = fsig(gg[128 + jG]);
            const float gv = ftanh(gg[256 + jG]);
            const float ov = fsig(gg[384 + jG]);
            c_reg = fv * c_reg + iv * gv;
            sm[M_HR + rG * 128 + jG] = ov * ftanh(c_reg) * ghv;
        }
        __syncthreads();

        cx = nx; cm = nm; cbeta = nbeta;
#pragma unroll
        for (int r = 0; r < 4; ++r) cgml[r] = ngml[r];
    }

    sm[M_RED + t] = loss;
    __syncthreads();
    for (int off = 128; off > 0; off >>= 1) { if (t < off) sm[M_RED + t] += sm[M_RED + t + off]; __syncthreads(); }
    if (t == 0) g_lossPartial[blockIdx.x] = sm[M_RED];
}

__global__ void rits_loss_final(float* __restrict__ out, int out_size) {
    __shared__ float red[NBLK];
    const int t = threadIdx.x;
    red[t] = g_lossPartial[t];
    __syncthreads();
    for (int off = NBLK / 2; off > 0; off >>= 1) { if (t < off) red[t] += red[t + off]; __syncthreads(); }
    const long long bsf = (long long)Bdim * Sdim * Fdim;
    if (t == 0 && (long long)out_size > bsf) out[bsf] = red[0] / (float)Sdim;
}

extern "C" void kernel_launch(void* const* d_in, const int* in_sizes, int n_in,
                              void* d_out, int out_size) {
    const float* x   = (const float*)d_in[0];
    const float* m   = (const float*)d_in[1];
    const float* tt  = (const float*)d_in[2];
    const float* Wdh = (const float*)d_in[3];
    const float* bdh = (const float*)d_in[4];
    const float* Wdm = (const float*)d_in[5];
    const float* bdm = (const float*)d_in[6];
    const float* Wtr = (const float*)d_in[7];
    const float* btr = (const float*)d_in[8];
    const float* Wfr = (const float*)d_in[9];
    const float* bfr = (const float*)d_in[10];
    const float* Wwc = (const float*)d_in[11];
    const float* bwc = (const float*)d_in[12];
    const float* Wih = (const float*)d_in[13];
    const float* Whh = (const float*)d_in[14];
    const float* bih = (const float*)d_in[15];
    const float* bhh = (const float*)d_in[16];
    float* out = (float*)d_out;

    cudaFuncSetAttribute(rits_pre, cudaFuncAttributeMaxDynamicSharedMemorySize, PRE_SMB);
    cudaFuncSetAttribute(rits_main, cudaFuncAttributeMaxDynamicSharedMemorySize, M_SMB);

    rits_pre<<<4832, 256, PRE_SMB>>>(m, tt, Wdh, bdh, Wdm, bdm, Wwc, bwc, Wih, bih, bhh, Whh);
    rits_main<<<NBLK, 256, M_SMB>>>(x, m, Wtr, btr, Wfr, bfr, Wih, Whh, out);
    rits_loss_final<<<1, NBLK>>>(out, out_size);
}

// round 14
// speedup vs baseline: 1.3987x; 1.0433x over previous
#include <cuda_runtime.h>

#define Bdim 256
#define Sdim 512
#define Fdim 64
#define Hdim 128
#define BS   (Bdim * Sdim)
#define NBLK 128           // 2 batch rows per block
#define KQ   28            // streamed Whh quad groups (k = 16..127)
#define NR   14            // register-resident q-groups of the streamed tail

__device__ float g_invDenom[Sdim];
__device__ float g_lossPartial[NBLK];
__device__ float g_WhhQ[KQ * 512 * 4];            // [(q*512+j)*4+r] = Whh[j][16+4q+r]
__device__ float g_gh[(size_t)BS * Hdim];         // gamma_h
__device__ float g_beta[(size_t)BS * Fdim];       // beta
__device__ float g_gml[(size_t)BS * 512];         // [b][s][j]: ml@WihMask^T + bio

typedef unsigned long long u64;
__device__ __forceinline__ u64 pk2(float lo, float hi) {
    u64 r; asm("mov.b64 %0,{%1,%2};" : "=l"(r) : "r"(__float_as_uint(lo)), "r"(__float_as_uint(hi))); return r;
}
__device__ __forceinline__ void up2(u64 v, float& lo, float& hi) {
    unsigned a, b; asm("mov.b64 {%0,%1},%2;" : "=r"(a), "=r"(b) : "l"(v));
    lo = __uint_as_float(a); hi = __uint_as_float(b);
}
__device__ __forceinline__ u64 ff2(u64 a, u64 b, u64 c) {
    u64 d; asm("fma.rn.f32x2 %0,%1,%2,%3;" : "=l"(d) : "l"(a), "l"(b), "l"(c)); return d;
}
__device__ __forceinline__ float fsig(float v) {
    const float e = __expf(-v);
    return __fdividef(1.0f, 1.0f + e);
}
__device__ __forceinline__ float ftanh(float v) {
    const float vc = fminf(fmaxf(v, -15.0f), 15.0f);
    const float e = __expf(2.0f * vc);
    return __fdividef(e - 1.0f, e + 1.0f);
}

// ================= small pre kernel: denom + whhq only =================
// blockIdx: [0,512) denom | [512,736) whhq
__global__ __launch_bounds__(256) void rits_pre(
    const float* __restrict__ m, const float* __restrict__ Whh)
{
    __shared__ float red[256];
    const int b = blockIdx.x, t = threadIdx.x;
    if (b < 512) {
        const int s = b;
        const float4* p = (const float4*)(m + (size_t)t * Sdim * Fdim + (size_t)s * Fdim);
        float sum = 0.f;
#pragma unroll
        for (int i = 0; i < 16; ++i) { float4 v = p[i]; sum += v.x + v.y + v.z + v.w; }
        red[t] = sum;
        __syncthreads();
        for (int off = 128; off > 0; off >>= 1) { if (t < off) red[t] += red[t + off]; __syncthreads(); }
        if (t == 0) g_invDenom[s] = 1.0f / (red[0] + 1e-5f);
    } else {
        const int i = (b - 512) * 256 + t;
        if (i < KQ * 512 * 4) {
            const int r = i & 3, j = (i >> 2) & 511, q = i >> 11;
            g_WhhQ[i] = Whh[j * Hdim + 16 + 4 * q + r];
        }
    }
}

// ================= main kernel: in-block precompute + sequential loop =================
#define M_WIHQ 0        // 32768: [q<16][j][4] = Wih[j][4q+r]
#define M_WHHR 32768    // 8192:  [q<4][j][4]  = Whh[j][4q+r]
#define M_WTRQ 40960    // 8192:  [q<32][f][4] = Wtr[f][4q+r]
#define M_WFRQ 49152    // 4096:  [q<16][f][4] = Wfr_m[f][4q+r]
#define M_HR   53248    // 256:  hRow[2][128]
#define M_XC   53504    // 128
#define M_CLC  53632    // 128
#define M_GT   53760    // 1024
#define M_BTR  54784
#define M_BFR  54848
#define M_RED  54912    // 256
#define M_SMF  55168
#define M_SMB  (M_SMF * 4)   // 220,672 B

#define FS2(WP0, WP1, AP, STR) do {                                     \
    const ulonglong2 w0_ = *(const ulonglong2*)(WP0);                   \
    const ulonglong2 w1_ = *(const ulonglong2*)(WP1);                   \
    { const ulonglong2 a_ = *(const ulonglong2*)(AP);                   \
      A00 = ff2(w0_.x, a_.x, A00); A00 = ff2(w0_.y, a_.y, A00);         \
      A10 = ff2(w1_.x, a_.x, A10); A10 = ff2(w1_.y, a_.y, A10); }       \
    { const ulonglong2 a_ = *(const ulonglong2*)((AP) + (STR));         \
      A01 = ff2(w0_.x, a_.x, A01); A01 = ff2(w0_.y, a_.y, A01);         \
      A11 = ff2(w1_.x, a_.x, A11); A11 = ff2(w1_.y, a_.y, A11); }       \
} while (0)

__global__ __launch_bounds__(256, 1) void rits_main(
    const float* __restrict__ x, const float* __restrict__ m, const float* __restrict__ tt,
    const float* __restrict__ Wdh, const float* __restrict__ bdh,
    const float* __restrict__ Wdm, const float* __restrict__ bdm,
    const float* __restrict__ Wtr, const float* __restrict__ btr,
    const float* __restrict__ Wfr, const float* __restrict__ bfr,
    const float* __restrict__ Wwc, const float* __restrict__ bwc,
    const float* __restrict__ Wih, const float* __restrict__ Whh,
    const float* __restrict__ bih, const float* __restrict__ bhh,
    float* __restrict__ out)
{
    extern __shared__ float sm[];
    const int t = threadIdx.x;
    const int b0 = blockIdx.x * 2;

    // ================= in-block precompute for own 2 batch rows =================
    {
        const int row = t >> 7, sP = (t >> 6) & 1, f = t & 63;  // staging / per-(row,s,f) roles
        const int hh = t & 127;                                  // gh compute role

        // ---- gamma_h: g_gh[(b0+row, s, h)] = exp(-relu(t_s . Wdh[h] + bdh[h])) ----
        for (int i = t; i < 8192; i += 256) {
            const int r = i & 1, h2 = (i >> 1) & 127, k2 = i >> 8;
            sm[(k2 * 128 + h2) * 2 + r] = Wdh[h2 * 64 + 2 * k2 + r];
        }
        if (t < 128) sm[8192 + t] = bdh[t];
        float pv = tt[((size_t)(b0 + row) * Sdim + sP) * 64 + f];
        __syncthreads();
        for (int it = 0; it < 256; ++it) {
            const int s0 = 2 * it;
            float* TL = sm + 8320 + (it & 1) * 256;
            TL[(row * 2 + sP) * 64 + f] = pv;
            __syncthreads();
            if (it < 255) pv = tt[((size_t)(b0 + row) * Sdim + s0 + 2 + sP) * 64 + f];
            u64 a0 = 0ULL, a1 = 0ULL;
            const float* x0 = TL + (row * 2) * 64;
            const float* x1 = x0 + 64;
#pragma unroll
            for (int k2 = 0; k2 < 32; ++k2) {
                const u64 w = *(const u64*)(sm + (k2 * 128 + hh) * 2);
                a0 = ff2(w, *(const u64*)(x0 + 2 * k2), a0);
                a1 = ff2(w, *(const u64*)(x1 + 2 * k2), a1);
            }
            const float bb = sm[8192 + hh];
            float lo, hi;
            up2(a0, lo, hi);
            g_gh[((size_t)(b0 + row) * Sdim + s0) * 128 + hh] = __expf(-fmaxf(lo + hi + bb, 0.f));
            up2(a1, lo, hi);
            g_gh[((size_t)(b0 + row) * Sdim + s0 + 1) * 128 + hh] = __expf(-fmaxf(lo + hi + bb, 0.f));
        }
        __syncthreads();

        // ---- beta: [gamma_m, ml] @ Wwc^T + bwc ----
        for (int i = t; i < 8192; i += 256) {
            const int r = i & 1, f2 = (i >> 1) & 63, k2 = i >> 7;
            sm[(k2 * 64 + f2) * 2 + r] = Wwc[f2 * 128 + 2 * k2 + r];
        }
        if (t < 64) { sm[8192 + t] = Wdm[t * 64 + t]; sm[8256 + t] = bdm[t]; sm[8320 + t] = bwc[t]; }
        float ptv = tt[((size_t)(b0 + row) * Sdim + sP) * 64 + f];
        float pmv = m[((size_t)(b0 + row) * Sdim + sP) * 64 + f];
        __syncthreads();
        for (int it = 0; it < 256; ++it) {
            const int s0 = 2 * it;
            float* CZ = sm + 8384 + (it & 1) * 512;
            CZ[(row * 2 + sP) * 128 + f]      = __expf(-fmaxf(ptv * sm[8192 + f] + sm[8256 + f], 0.f));
            CZ[(row * 2 + sP) * 128 + 64 + f] = pmv;
            __syncthreads();
            if (it < 255) {
                ptv = tt[((size_t)(b0 + row) * Sdim + s0 + 2 + sP) * 64 + f];
                pmv = m[((size_t)(b0 + row) * Sdim + s0 + 2 + sP) * 64 + f];
            }
            u64 aA = 0ULL, aB = 0ULL;
            const float* xz = CZ + (row * 2 + sP) * 128;
#pragma unroll
            for (int k2 = 0; k2 < 64; k2 += 2) {
                aA = ff2(*(const u64*)(sm + (k2 * 64 + f) * 2), *(const u64*)(xz + 2 * k2), aA);
                aB = ff2(*(const u64*)(sm + ((k2 + 1) * 64 + f) * 2), *(const u64*)(xz + 2 * (k2 + 1)), aB);
            }
            float lA, hA, lB, hB;
            up2(aA, lA, hA); up2(aB, lB, hB);
            g_beta[((size_t)(b0 + row) * Sdim + s0 + sP) * 64 + f] = (lA + hA) + (lB + hB) + sm[8320 + f];
        }
        __syncthreads();

        // ---- gml: ml @ WihMask^T + bih + bhh (k-pair packed, zero pk2) ----
        for (int i = t; i < 32768; i += 256) {
            const int r = i & 1, j = (i >> 1) & 511, k2 = i >> 10;
            sm[(k2 * 512 + j) * 2 + r] = Wih[j * 128 + 64 + 2 * k2 + r];
        }
        for (int i = t; i < 512; i += 256) sm[32768 + i] = bih[i] + bhh[i];
        const int j0p = t, j1p = t + 256;
        float pm2 = m[((size_t)(b0 + row) * Sdim + sP) * 64 + f];
        __syncthreads();
        for (int it = 0; it < 256; ++it) {
            const int s0 = 2 * it;
            float* MB = sm + 33280 + (it & 1) * 256;
            MB[(row * 2 + sP) * 64 + f] = pm2;
            __syncthreads();
            if (it < 255) pm2 = m[((size_t)(b0 + row) * Sdim + s0 + 2 + sP) * 64 + f];
            u64 a00 = 0ULL, a01 = 0ULL, a02 = 0ULL, a03 = 0ULL;
            u64 a10 = 0ULL, a11 = 0ULL, a12 = 0ULL, a13 = 0ULL;
#pragma unroll
            for (int k2 = 0; k2 < 32; ++k2) {
                const u64 w0 = *(const u64*)(sm + (k2 * 512 + j0p) * 2);
                const u64 w1 = *(const u64*)(sm + (k2 * 512 + j1p) * 2);
                const u64 x00 = *(const u64*)(MB + 0 * 64 + 2 * k2);   // row0, s0
                const u64 x01 = *(const u64*)(MB + 1 * 64 + 2 * k2);   // row0, s0+1
                const u64 x10 = *(const u64*)(MB + 2 * 64 + 2 * k2);   // row1, s0
                const u64 x11 = *(const u64*)(MB + 3 * 64 + 2 * k2);   // row1, s0+1
                a00 = ff2(w0, x00, a00); a01 = ff2(w0, x01, a01);
                a02 = ff2(w0, x10, a02); a03 = ff2(w0, x11, a03);
                a10 = ff2(w1, x00, a10); a11 = ff2(w1, x01, a11);
                a12 = ff2(w1, x10, a12); a13 = ff2(w1, x11, a13);
            }
            const float bj0 = sm[32768 + j0p], bj1 = sm[32768 + j1p];
            float lo, hi;
            up2(a00, lo, hi); g_gml[((size_t)(b0 + 0) * Sdim + s0) * 512 + j0p]     = lo + hi + bj0;
            up2(a01, lo, hi); g_gml[((size_t)(b0 + 0) * Sdim + s0 + 1) * 512 + j0p] = lo + hi + bj0;
            up2(a02, lo, hi); g_gml[((size_t)(b0 + 1) * Sdim + s0) * 512 + j0p]     = lo + hi + bj0;
            up2(a03, lo, hi); g_gml[((size_t)(b0 + 1) * Sdim + s0 + 1) * 512 + j0p] = lo + hi + bj0;
            up2(a10, lo, hi); g_gml[((size_t)(b0 + 0) * Sdim + s0) * 512 + j1p]     = lo + hi + bj1;
            up2(a11, lo, hi); g_gml[((size_t)(b0 + 0) * Sdim + s0 + 1) * 512 + j1p] = lo + hi + bj1;
            up2(a12, lo, hi); g_gml[((size_t)(b0 + 1) * Sdim + s0) * 512 + j1p]     = lo + hi + bj1;
            up2(a13, lo, hi); g_gml[((size_t)(b0 + 1) * Sdim + s0 + 1) * 512 + j1p] = lo + hi + bj1;
        }
        __syncthreads();
    }

    // ================= load main-loop weight tiles =================
    for (int i = t; i < 32768; i += 256) { const int r = i & 3, j = (i >> 2) & 511, q = i >> 11; sm[M_WIHQ + i] = Wih[j * 128 + 4 * q + r]; }
    for (int i = t; i < 8192; i += 256)  { const int r = i & 3, j = (i >> 2) & 511, q = i >> 11; sm[M_WHHR + i] = Whh[j * 128 + 4 * q + r]; }
    for (int i = t; i < 8192; i += 256)  { const int r = i & 3, f = (i >> 2) & 63, q = i >> 8; sm[M_WTRQ + i] = Wtr[f * 128 + 4 * q + r]; }
    for (int i = t; i < 4096; i += 256)  { const int r = i & 3, f = (i >> 2) & 63, q = i >> 8; const int k = 4 * q + r; sm[M_WFRQ + i] = (k == f) ? 0.f : Wfr[f * 64 + k]; }
    if (t < 64) { sm[M_BTR + t] = btr[t]; sm[M_BFR + t] = bfr[t]; }
    sm[M_HR + t] = 0.f;
    float c_reg = 0.f, loss = 0.f;

    const int rE = t >> 6, fE = t & 63;
    const int j0 = t, j1 = t + 256;
    const int rG = t >> 7, jG = t & 127;

    u64 rw[NR * 4];
#pragma unroll
    for (int q = 0; q < NR; ++q) {
        const ulonglong2 a = *(const ulonglong2*)(g_WhhQ + ((size_t)q * 512 + j0) * 4);
        const ulonglong2 bq = *(const ulonglong2*)(g_WhhQ + ((size_t)q * 512 + j1) * 4);
        rw[4 * q] = a.x; rw[4 * q + 1] = a.y; rw[4 * q + 2] = bq.x; rw[4 * q + 3] = bq.y;
    }

    float cx = 0.f, cm = 0.f, cbeta = 0.f;
    if (t < 128) {
        const size_t idxP = ((size_t)(b0 + rE) * Sdim) * Fdim + fE;
        cx = x[idxP]; cm = m[idxP]; cbeta = g_beta[idxP];
    }
    float cgml[4];
    cgml[0] = g_gml[((size_t)(b0 + 0) * Sdim) * 512 + j0];
    cgml[1] = g_gml[((size_t)(b0 + 1) * Sdim) * 512 + j0];
    cgml[2] = g_gml[((size_t)(b0 + 0) * Sdim) * 512 + j1];
    cgml[3] = g_gml[((size_t)(b0 + 1) * Sdim) * 512 + j1];
    __syncthreads();

    for (int s = 0; s < Sdim; ++s) {
        const int sn = (s < Sdim - 1) ? s + 1 : s;
        const float ghv = g_gh[((size_t)(b0 + rG) * Sdim + sn) * Hdim + jG];
        float nx = 0.f, nm = 0.f, nbeta = 0.f, cInv = 0.f;
        if (t < 128) {
            cInv = g_invDenom[s];
            const size_t idxN = ((size_t)(b0 + rE) * Sdim + sn) * Fdim + fE;
            nx = x[idxN]; nm = m[idxN]; nbeta = g_beta[idxN];
        }
        float ngml[4];
        ngml[0] = g_gml[((size_t)(b0 + 0) * Sdim + sn) * 512 + j0];
        ngml[1] = g_gml[((size_t)(b0 + 1) * Sdim + sn) * 512 + j0];
        ngml[2] = g_gml[((size_t)(b0 + 0) * Sdim + sn) * 512 + j1];
        ngml[3] = g_gml[((size_t)(b0 + 1) * Sdim + sn) * 512 + j1];

        // C: xl_hat (4 chains) ; xl_c
        float xh = 0.f;
        if (t < 128) {
            u64 ac0 = 0ULL, ac1 = 0ULL, ac2 = 0ULL, ac3 = 0ULL;
            const float* hr = sm + M_HR + rE * 128;
#pragma unroll
            for (int q = 0; q < 32; q += 4) {
                { const ulonglong2 w = *(const ulonglong2*)(sm + M_WTRQ + (q * 64 + fE) * 4);
                  const ulonglong2 a = *(const ulonglong2*)(hr + 4 * q);
                  ac0 = ff2(w.x, a.x, ac0); ac0 = ff2(w.y, a.y, ac0); }
                { const ulonglong2 w = *(const ulonglong2*)(sm + M_WTRQ + ((q + 1) * 64 + fE) * 4);
                  const ulonglong2 a = *(const ulonglong2*)(hr + 4 * (q + 1));
                  ac1 = ff2(w.x, a.x, ac1); ac1 = ff2(w.y, a.y, ac1); }
                { const ulonglong2 w = *(const ulonglong2*)(sm + M_WTRQ + ((q + 2) * 64 + fE) * 4);
                  const ulonglong2 a = *(const ulonglong2*)(hr + 4 * (q + 2));
                  ac2 = ff2(w.x, a.x, ac2); ac2 = ff2(w.y, a.y, ac2); }
                { const ulonglong2 w = *(const ulonglong2*)(sm + M_WTRQ + ((q + 3) * 64 + fE) * 4);
                  const ulonglong2 a = *(const ulonglong2*)(hr + 4 * (q + 3));
                  ac3 = ff2(w.x, a.x, ac3); ac3 = ff2(w.y, a.y, ac3); }
            }
            float l0, h0, l1, h1, l2, h2, l3, h3;
            up2(ac0, l0, h0); up2(ac1, l1, h1); up2(ac2, l2, h2); up2(ac3, l3, h3);
            xh = sm[M_BTR + fE] + ((l0 + h0) + (l1 + h1)) + ((l2 + h2) + (l3 + h3));
            sm[M_XC + rE * 64 + fE] = cm * cx + (1.f - cm) * xh;
        }
        __syncthreads();

        // D+E: zl_hat (2 chains), cl_hat, cl_c, output, loss
        if (t < 128) {
            u64 ac0 = 0ULL, ac1 = 0ULL;
            const float* xr = sm + M_XC + rE * 64;
#pragma unroll
            for (int q = 0; q < 16; q += 2) {
                { const ulonglong2 w = *(const ulonglong2*)(sm + M_WFRQ + (q * 64 + fE) * 4);
                  const ulonglong2 a = *(const ulonglong2*)(xr + 4 * q);
                  ac0 = ff2(w.x, a.x, ac0); ac0 = ff2(w.y, a.y, ac0); }
                { const ulonglong2 w = *(const ulonglong2*)(sm + M_WFRQ + ((q + 1) * 64 + fE) * 4);
                  const ulonglong2 a = *(const ulonglong2*)(xr + 4 * (q + 1));
                  ac1 = ff2(w.x, a.x, ac1); ac1 = ff2(w.y, a.y, ac1); }
            }
            float l0, h0, l1, h1;
            up2(ac0, l0, h0); up2(ac1, l1, h1);
            const float zh = sm[M_BFR + fE] + (l0 + h0) + (l1 + h1);
            const float ch = cbeta * zh + (1.f - cbeta) * xh;
            const float cc = cm * cx + (1.f - cm) * ch;
            sm[M_CLC + rE * 64 + fE] = cc;
            out[((size_t)(b0 + rE) * Sdim + s) * Fdim + fE] = cc;
            const float d1 = cx - xh, d2 = cx - zh, d3 = cx - ch;
            loss += cm * (d1 * d1 + d2 * d2 + d3 * d3) * cInv;
        }
        __syncthreads();

        // F: gates = gml + clc @ WihClc^T + h @ Whh^T
        {
            u64 A00 = 0ULL, A01 = 0ULL, A10 = 0ULL, A11 = 0ULL;
#pragma unroll
            for (int q = 0; q < 16; ++q)
                FS2(sm + M_WIHQ + (q * 512 + j0) * 4,
                    sm + M_WIHQ + (q * 512 + j1) * 4,
                    sm + M_CLC + 4 * q, 64);
#pragma unroll
            for (int q = 0; q < 4; ++q)
                FS2(sm + M_WHHR + (q * 512 + j0) * 4,
                    sm + M_WHHR + (q * 512 + j1) * 4,
                    sm + M_HR + 4 * q, 128);
#pragma unroll
            for (int q = 0; q < NR; ++q) {
                const float* AP = sm + M_HR + 16 + 4 * q;
                { const ulonglong2 a_ = *(const ulonglong2*)(AP);
                  A00 = ff2(rw[4 * q], a_.x, A00); A00 = ff2(rw[4 * q + 1], a_.y, A00);
                  A10 = ff2(rw[4 * q + 2], a_.x, A10); A10 = ff2(rw[4 * q + 3], a_.y, A10); }
                { const ulonglong2 a_ = *(const ulonglong2*)(AP + 128);
                  A01 = ff2(rw[4 * q], a_.x, A01); A01 = ff2(rw[4 * q + 1], a_.y, A01);
                  A11 = ff2(rw[4 * q + 2], a_.x, A11); A11 = ff2(rw[4 * q + 3], a_.y, A11); }
            }
#pragma unroll 7
            for (int q = NR; q < KQ; ++q)
                FS2(g_WhhQ + ((size_t)q * 512 + j0) * 4,
                    g_WhhQ + ((size_t)q * 512 + j1) * 4,
                    sm + M_HR + 16 + 4 * q, 128);
            float lo, hi;
            up2(A00, lo, hi); sm[M_GT + 0 * 512 + j0] = lo + hi + cgml[0];
            up2(A01, lo, hi); sm[M_GT + 1 * 512 + j0] = lo + hi + cgml[1];
            up2(A10, lo, hi); sm[M_GT + 0 * 512 + j1] = lo + hi + cgml[2];
            up2(A11, lo, hi); sm[M_GT + 1 * 512 + j1] = lo + hi + cgml[3];
        }
        __syncthreads();

        // G: LSTM update + apply gamma_h(s+1)
        {
            const float* gg = sm + M_GT + rG * 512;
            const float iv = fsig(gg[jG]);
            const float fv = fsig(gg[128 + jG]);
            const float gv = ftanh(gg[256 + jG]);
            const float ov = fsig(gg[384 + jG]);
            c_reg = fv * c_reg + iv * gv;
            sm[M_HR + rG * 128 + jG] = ov * ftanh(c_reg) * ghv;
        }
        __syncthreads();

        cx = nx; cm = nm; cbeta = nbeta;
#pragma unroll
        for (int r = 0; r < 4; ++r) cgml[r] = ngml[r];
    }

    sm[M_RED + t] = loss;
    __syncthreads();
    for (int off = 128; off > 0; off >>= 1) { if (t < off) sm[M_RED + t] += sm[M_RED + t + off]; __syncthreads(); }
    if (t == 0) g_lossPartial[blockIdx.x] = sm[M_RED];
}

__global__ void rits_loss_final(float* __restrict__ out, int out_size) {
    __shared__ float red[NBLK];
    const int t = threadIdx.x;
    red[t] = g_lossPartial[t];
    __syncthreads();
    for (int off = NBLK / 2; off > 0; off >>= 1) { if (t < off) red[t] += red[t + off]; __syncthreads(); }
    const long long bsf = (long long)Bdim * Sdim * Fdim;
    if (t == 0 && (long long)out_size > bsf) out[bsf] = red[0] / (float)Sdim;
}

extern "C" void kernel_launch(void* const* d_in, const int* in_sizes, int n_in,
                              void* d_out, int out_size) {
    const float* x   = (const float*)d_in[0];
    const float* m   = (const float*)d_in[1];
    const float* tt  = (const float*)d_in[2];
    const float* Wdh = (const float*)d_in[3];
    const float* bdh = (const float*)d_in[4];
    const float* Wdm = (const float*)d_in[5];
    const float* bdm = (const float*)d_in[6];
    const float* Wtr = (const float*)d_in[7];
    const float* btr = (const float*)d_in[8];
    const float* Wfr = (const float*)d_in[9];
    const float* bfr = (const float*)d_in[10];
    const float* Wwc = (const float*)d_in[11];
    const float* bwc = (const float*)d_in[12];
    const float* Wih = (const float*)d_in[13];
    const float* Whh = (const float*)d_in[14];
    const float* bih = (const float*)d_in[15];
    const float* bhh = (const float*)d_in[16];
    float* out = (float*)d_out;

    cudaFuncSetAttribute(rits_main, cudaFuncAttributeMaxDynamicSharedMemorySize, M_SMB);

    rits_pre<<<736, 256>>>(m, Whh);
    rits_main<<<NBLK, 256, M_SMB>>>(x, m, tt, Wdh, bdh, Wdm, bdm, Wtr, btr,
                                    Wfr, bfr, Wwc, bwc, Wih, Whh, bih, bhh, out);
    rits_loss_final<<<1, NBLK>>>(out, out_size);
}

// round 15
// speedup vs baseline: 1.4085x; 1.0070x over previous
#include <cuda_runtime.h>

#define Bdim 256
#define Sdim 512
#define Fdim 64
#define Hdim 128
#define BS   (Bdim * Sdim)
#define NBLK 128           // 2 batch rows per block
#define KQ   28            // streamed Whh quad groups (k = 16..127)
#define NR   14            // register-resident q-groups of the streamed tail

__device__ float g_invDenom[Sdim];
__device__ float g_lossPartial[NBLK];
__device__ float g_WhhQ[KQ * 512 * 4];            // [(q*512+j)*4+r] = Whh[j][16+4q+r]
__device__ float g_gh[(size_t)BS * Hdim];         // gamma_h
__device__ float g_beta[(size_t)BS * Fdim];       // beta
__device__ float g_gml[(size_t)BS * 512];         // [b][s][j]: ml@WihMask^T + bio

typedef unsigned long long u64;
__device__ __forceinline__ void up2(u64 v, float& lo, float& hi) {
    unsigned a, b; asm("mov.b64 {%0,%1},%2;" : "=r"(a), "=r"(b) : "l"(v));
    lo = __uint_as_float(a); hi = __uint_as_float(b);
}
__device__ __forceinline__ u64 ff2(u64 a, u64 b, u64 c) {
    u64 d; asm("fma.rn.f32x2 %0,%1,%2,%3;" : "=l"(d) : "l"(a), "l"(b), "l"(c)); return d;
}
__device__ __forceinline__ float fsig(float v) {
    const float e = __expf(-v);
    return __fdividef(1.0f, 1.0f + e);
}
__device__ __forceinline__ float ftanh(float v) {
    const float vc = fminf(fmaxf(v, -15.0f), 15.0f);
    const float e = __expf(2.0f * vc);
    return __fdividef(e - 1.0f, e + 1.0f);
}

// ================= small pre kernel: denom + whhq only =================
__global__ __launch_bounds__(256) void rits_pre(
    const float* __restrict__ m, const float* __restrict__ Whh)
{
    __shared__ float red[256];
    const int b = blockIdx.x, t = threadIdx.x;
    if (b < 512) {
        const int s = b;
        const float4* p = (const float4*)(m + (size_t)t * Sdim * Fdim + (size_t)s * Fdim);
        float sum = 0.f;
#pragma unroll
        for (int i = 0; i < 16; ++i) { float4 v = p[i]; sum += v.x + v.y + v.z + v.w; }
        red[t] = sum;
        __syncthreads();
        for (int off = 128; off > 0; off >>= 1) { if (t < off) red[t] += red[t + off]; __syncthreads(); }
        if (t == 0) g_invDenom[s] = 1.0f / (red[0] + 1e-5f);
    } else {
        const int i = (b - 512) * 256 + t;
        if (i < KQ * 512 * 4) {
            const int r = i & 3, j = (i >> 2) & 511, q = i >> 11;
            g_WhhQ[i] = Whh[j * Hdim + 16 + 4 * q + r];
        }
    }
}

// ================= main kernel =================
// precompute smem layout (floats)
#define PW_DH  0        // 8192:  [(k2*128+h)*2+r] = Wdh[h][2k2+r]
#define PB_DH  8192     // 128
#define PW_WC  8320     // 8192:  [(k2*64+f)*2+r] = Wwc[f][2k2+r], k2 0..63
#define PD_WDM 16512    // 64
#define PB_DM  16576    // 64
#define PB_WC  16640    // 64
#define PW_IH  16704    // 32768: [(k2*512+j)*2+r] = Wih[j][64+2k2+r]
#define PB_IO  49472    // 512
#define P_TL   49984    // [2][4][64]
#define P_MB   50496    // [2][4][64]
#define P_GM   51008    // [2][4][64]
// main-loop layout
#define M_WIHQ 0        // 32768: [q<16][j][4] = Wih[j][4q+r]
#define M_WHHR 32768    // 8192:  [q<4][j][4]  = Whh[j][4q+r]
#define M_WTRQ 40960    // 8192:  [q<32][f][4] = Wtr[f][4q+r]
#define M_WFRQ 49152    // 4096:  [q<16][f][4] = Wfr_m[f][4q+r]
#define M_HR   53248    // 256:  hRow[2][128]
#define M_XC   53504    // 128
#define M_CLC  53632    // 128
#define M_GT   53760    // 1024
#define M_BTR  54784
#define M_BFR  54848
#define M_RED  54912    // 256
#define M_SMF  55168
#define M_SMB  (M_SMF * 4)   // 220,672 B

#define FS2(WP0, WP1, AP, STR) do {                                     \
    const ulonglong2 w0_ = *(const ulonglong2*)(WP0);                   \
    const ulonglong2 w1_ = *(const ulonglong2*)(WP1);                   \
    { const ulonglong2 a_ = *(const ulonglong2*)(AP);                   \
      A00 = ff2(w0_.x, a_.x, A00); A00 = ff2(w0_.y, a_.y, A00);         \
      A10 = ff2(w1_.x, a_.x, A10); A10 = ff2(w1_.y, a_.y, A10); }       \
    { const ulonglong2 a_ = *(const ulonglong2*)((AP) + (STR));         \
      A01 = ff2(w0_.x, a_.x, A01); A01 = ff2(w0_.y, a_.y, A01);         \
      A11 = ff2(w1_.x, a_.x, A11); A11 = ff2(w1_.y, a_.y, A11); }       \
} while (0)

__global__ __launch_bounds__(256, 1) void rits_main(
    const float* __restrict__ x, const float* __restrict__ m, const float* __restrict__ tt,
    const float* __restrict__ Wdh, const float* __restrict__ bdh,
    const float* __restrict__ Wdm, const float* __restrict__ bdm,
    const float* __restrict__ Wtr, const float* __restrict__ btr,
    const float* __restrict__ Wfr, const float* __restrict__ bfr,
    const float* __restrict__ Wwc, const float* __restrict__ bwc,
    const float* __restrict__ Wih, const float* __restrict__ Whh,
    const float* __restrict__ bih, const float* __restrict__ bhh,
    float* __restrict__ out)
{
    extern __shared__ float sm[];
    const int t = threadIdx.x;
    const int b0 = blockIdx.x * 2;

    // ============== single-pass in-block precompute (gh + beta + gml) ==============
    {
        const int row = t >> 7, sP = (t >> 6) & 1, f = t & 63;
        const int hh = t & 127;
        const int j0p = t, j1p = t + 256;

        for (int i = t; i < 8192; i += 256) { const int r = i & 1, h2 = (i >> 1) & 127, k2 = i >> 8; sm[PW_DH + (k2 * 128 + h2) * 2 + r] = Wdh[h2 * 64 + 2 * k2 + r]; }
        if (t < 128) sm[PB_DH + t] = bdh[t];
        for (int i = t; i < 8192; i += 256) { const int r = i & 1, f2 = (i >> 1) & 63, k2 = i >> 7; sm[PW_WC + (k2 * 64 + f2) * 2 + r] = Wwc[f2 * 128 + 2 * k2 + r]; }
        if (t < 64) { sm[PD_WDM + t] = Wdm[t * 64 + t]; sm[PB_DM + t] = bdm[t]; sm[PB_WC + t] = bwc[t]; }
        for (int i = t; i < 32768; i += 256) { const int r = i & 1, j = (i >> 1) & 511, k2 = i >> 10; sm[PW_IH + (k2 * 512 + j) * 2 + r] = Wih[j * 128 + 64 + 2 * k2 + r]; }
        for (int i = t; i < 512; i += 256) sm[PB_IO + i] = bih[i] + bhh[i];

        float ptv = tt[((size_t)(b0 + row) * Sdim + sP) * 64 + f];
        float pmv = m[((size_t)(b0 + row) * Sdim + sP) * 64 + f];
        __syncthreads();

        for (int it = 0; it < 256; ++it) {
            const int s0 = 2 * it;
            const int buf = it & 1;
            float* TL = sm + P_TL + buf * 256;
            float* MB = sm + P_MB + buf * 256;
            float* GM = sm + P_GM + buf * 256;
            const float ctv = ptv;
            TL[(row * 2 + sP) * 64 + f] = ptv;
            MB[(row * 2 + sP) * 64 + f] = pmv;
            __syncthreads();
            if (it < 255) {
                ptv = tt[((size_t)(b0 + row) * Sdim + s0 + 2 + sP) * 64 + f];
                pmv = m[((size_t)(b0 + row) * Sdim + s0 + 2 + sP) * 64 + f];
            }
            // gamma_m into GM
            GM[(row * 2 + sP) * 64 + f] = __expf(-fmaxf(ctv * sm[PD_WDM + f] + sm[PB_DM + f], 0.f));
            // gh for (row, hh), both s
            {
                u64 a0 = 0ULL, a1 = 0ULL;
                const float* x0 = TL + (row * 2) * 64;
                const float* x1 = x0 + 64;
#pragma unroll
                for (int k2 = 0; k2 < 32; ++k2) {
                    const u64 w = *(const u64*)(sm + PW_DH + (k2 * 128 + hh) * 2);
                    a0 = ff2(w, *(const u64*)(x0 + 2 * k2), a0);
                    a1 = ff2(w, *(const u64*)(x1 + 2 * k2), a1);
                }
                const float bb = sm[PB_DH + hh];
                float lo, hi;
                up2(a0, lo, hi);
                g_gh[((size_t)(b0 + row) * Sdim + s0) * 128 + hh] = __expf(-fmaxf(lo + hi + bb, 0.f));
                up2(a1, lo, hi);
                g_gh[((size_t)(b0 + row) * Sdim + s0 + 1) * 128 + hh] = __expf(-fmaxf(lo + hi + bb, 0.f));
            }
            __syncthreads();
            // beta for (row, sP, f)
            {
                u64 aA = 0ULL, aB = 0ULL;
                const float* gmp = GM + (row * 2 + sP) * 64;
                const float* mlp = MB + (row * 2 + sP) * 64;
#pragma unroll
                for (int k2 = 0; k2 < 32; ++k2) {
                    aA = ff2(*(const u64*)(sm + PW_WC + (k2 * 64 + f) * 2), *(const u64*)(gmp + 2 * k2), aA);
                    aB = ff2(*(const u64*)(sm + PW_WC + ((32 + k2) * 64 + f) * 2), *(const u64*)(mlp + 2 * k2), aB);
                }
                float lA, hA, lB, hB;
                up2(aA, lA, hA); up2(aB, lB, hB);
                g_beta[((size_t)(b0 + row) * Sdim + s0 + sP) * 64 + f] = (lA + hA) + (lB + hB) + sm[PB_WC + f];
            }
            // gml for j0p/j1p, 2 rows x 2 s
            {
                u64 a00 = 0ULL, a01 = 0ULL, a02 = 0ULL, a03 = 0ULL;
                u64 a10 = 0ULL, a11 = 0ULL, a12 = 0ULL, a13 = 0ULL;
#pragma unroll
                for (int k2 = 0; k2 < 32; ++k2) {
                    const u64 w0 = *(const u64*)(sm + PW_IH + (k2 * 512 + j0p) * 2);
                    const u64 w1 = *(const u64*)(sm + PW_IH + (k2 * 512 + j1p) * 2);
                    const u64 x00 = *(const u64*)(MB + 0 * 64 + 2 * k2);
                    const u64 x01 = *(const u64*)(MB + 1 * 64 + 2 * k2);
                    const u64 x10 = *(const u64*)(MB + 2 * 64 + 2 * k2);
                    const u64 x11 = *(const u64*)(MB + 3 * 64 + 2 * k2);
                    a00 = ff2(w0, x00, a00); a01 = ff2(w0, x01, a01);
                    a02 = ff2(w0, x10, a02); a03 = ff2(w0, x11, a03);
                    a10 = ff2(w1, x00, a10); a11 = ff2(w1, x01, a11);
                    a12 = ff2(w1, x10, a12); a13 = ff2(w1, x11, a13);
                }
                const float bj0 = sm[PB_IO + j0p], bj1 = sm[PB_IO + j1p];
                float lo, hi;
                up2(a00, lo, hi); g_gml[((size_t)(b0 + 0) * Sdim + s0) * 512 + j0p]     = lo + hi + bj0;
                up2(a01, lo, hi); g_gml[((size_t)(b0 + 0) * Sdim + s0 + 1) * 512 + j0p] = lo + hi + bj0;
                up2(a02, lo, hi); g_gml[((size_t)(b0 + 1) * Sdim + s0) * 512 + j0p]     = lo + hi + bj0;
                up2(a03, lo, hi); g_gml[((size_t)(b0 + 1) * Sdim + s0 + 1) * 512 + j0p] = lo + hi + bj0;
                up2(a10, lo, hi); g_gml[((size_t)(b0 + 0) * Sdim + s0) * 512 + j1p]     = lo + hi + bj1;
                up2(a11, lo, hi); g_gml[((size_t)(b0 + 0) * Sdim + s0 + 1) * 512 + j1p] = lo + hi + bj1;
                up2(a12, lo, hi); g_gml[((size_t)(b0 + 1) * Sdim + s0) * 512 + j1p]     = lo + hi + bj1;
                up2(a13, lo, hi); g_gml[((size_t)(b0 + 1) * Sdim + s0 + 1) * 512 + j1p] = lo + hi + bj1;
            }
        }
        __syncthreads();
    }

    // ================= load main-loop weight tiles =================
    for (int i = t; i < 32768; i += 256) { const int r = i & 3, j = (i >> 2) & 511, q = i >> 11; sm[M_WIHQ + i] = Wih[j * 128 + 4 * q + r]; }
    for (int i = t; i < 8192; i += 256)  { const int r = i & 3, j = (i >> 2) & 511, q = i >> 11; sm[M_WHHR + i] = Whh[j * 128 + 4 * q + r]; }
    for (int i = t; i < 8192; i += 256)  { const int r = i & 3, f = (i >> 2) & 63, q = i >> 8; sm[M_WTRQ + i] = Wtr[f * 128 + 4 * q + r]; }
    for (int i = t; i < 4096; i += 256)  { const int r = i & 3, f = (i >> 2) & 63, q = i >> 8; const int k = 4 * q + r; sm[M_WFRQ + i] = (k == f) ? 0.f : Wfr[f * 64 + k]; }
    if (t < 64) { sm[M_BTR + t] = btr[t]; sm[M_BFR + t] = bfr[t]; }
    sm[M_HR + t] = 0.f;
    float c_reg = 0.f, loss = 0.f;

    const int rE = t >> 6, fE = t & 63;
    const int j0 = t, j1 = t + 256;
    const int rG = t >> 7, jG = t & 127;

    u64 rw[NR * 4];
#pragma unroll
    for (int q = 0; q < NR; ++q) {
        const ulonglong2 a = *(const ulonglong2*)(g_WhhQ + ((size_t)q * 512 + j0) * 4);
        const ulonglong2 bq = *(const ulonglong2*)(g_WhhQ + ((size_t)q * 512 + j1) * 4);
        rw[4 * q] = a.x; rw[4 * q + 1] = a.y; rw[4 * q + 2] = bq.x; rw[4 * q + 3] = bq.y;
    }

    float cx = 0.f, cm = 0.f, cbeta = 0.f;
    if (t < 128) {
        const size_t idxP = ((size_t)(b0 + rE) * Sdim) * Fdim + fE;
        cx = x[idxP]; cm = m[idxP]; cbeta = g_beta[idxP];
    }
    float cgml[4];
    cgml[0] = g_gml[((size_t)(b0 + 0) * Sdim) * 512 + j0];
    cgml[1] = g_gml[((size_t)(b0 + 1) * Sdim) * 512 + j0];
    cgml[2] = g_gml[((size_t)(b0 + 0) * Sdim) * 512 + j1];
    cgml[3] = g_gml[((size_t)(b0 + 1) * Sdim) * 512 + j1];
    __syncthreads();

    for (int s = 0; s < Sdim; ++s) {
        const int sn = (s < Sdim - 1) ? s + 1 : s;
        const float ghv = g_gh[((size_t)(b0 + rG) * Sdim + sn) * Hdim + jG];
        float nx = 0.f, nm = 0.f, nbeta = 0.f, cInv = 0.f;
        if (t < 128) {
            cInv = g_invDenom[s];
            const size_t idxN = ((size_t)(b0 + rE) * Sdim + sn) * Fdim + fE;
            nx = x[idxN]; nm = m[idxN]; nbeta = g_beta[idxN];
        }
        float ngml[4];
        ngml[0] = g_gml[((size_t)(b0 + 0) * Sdim + sn) * 512 + j0];
        ngml[1] = g_gml[((size_t)(b0 + 1) * Sdim + sn) * 512 + j0];
        ngml[2] = g_gml[((size_t)(b0 + 0) * Sdim + sn) * 512 + j1];
        ngml[3] = g_gml[((size_t)(b0 + 1) * Sdim + sn) * 512 + j1];

        // C: xl_hat (4 chains) ; xl_c
        float xh = 0.f;
        if (t < 128) {
            u64 ac0 = 0ULL, ac1 = 0ULL, ac2 = 0ULL, ac3 = 0ULL;
            const float* hr = sm + M_HR + rE * 128;
#pragma unroll
            for (int q = 0; q < 32; q += 4) {
                { const ulonglong2 w = *(const ulonglong2*)(sm + M_WTRQ + (q * 64 + fE) * 4);
                  const ulonglong2 a = *(const ulonglong2*)(hr + 4 * q);
                  ac0 = ff2(w.x, a.x, ac0); ac0 = ff2(w.y, a.y, ac0); }
                { const ulonglong2 w = *(const ulonglong2*)(sm + M_WTRQ + ((q + 1) * 64 + fE) * 4);
                  const ulonglong2 a = *(const ulonglong2*)(hr + 4 * (q + 1));
                  ac1 = ff2(w.x, a.x, ac1); ac1 = ff2(w.y, a.y, ac1); }
                { const ulonglong2 w = *(const ulonglong2*)(sm + M_WTRQ + ((q + 2) * 64 + fE) * 4);
                  const ulonglong2 a = *(const ulonglong2*)(hr + 4 * (q + 2));
                  ac2 = ff2(w.x, a.x, ac2); ac2 = ff2(w.y, a.y, ac2); }
                { const ulonglong2 w = *(const ulonglong2*)(sm + M_WTRQ + ((q + 3) * 64 + fE) * 4);
                  const ulonglong2 a = *(const ulonglong2*)(hr + 4 * (q + 3));
                  ac3 = ff2(w.x, a.x, ac3); ac3 = ff2(w.y, a.y, ac3); }
            }
            float l0, h0, l1, h1, l2, h2, l3, h3;
            up2(ac0, l0, h0); up2(ac1, l1, h1); up2(ac2, l2, h2); up2(ac3, l3, h3);
            xh = sm[M_BTR + fE] + ((l0 + h0) + (l1 + h1)) + ((l2 + h2) + (l3 + h3));
            sm[M_XC + rE * 64 + fE] = cm * cx + (1.f - cm) * xh;
        }
        __syncthreads();

        // D+E: zl_hat (2 chains), cl_hat, cl_c, output, loss
        if (t < 128) {
            u64 ac0 = 0ULL, ac1 = 0ULL;
            const float* xr = sm + M_XC + rE * 64;
#pragma unroll
            for (int q = 0; q < 16; q += 2) {
                { const ulonglong2 w = *(const ulonglong2*)(sm + M_WFRQ + (q * 64 + fE) * 4);
                  const ulonglong2 a = *(const ulonglong2*)(xr + 4 * q);
                  ac0 = ff2(w.x, a.x, ac0); ac0 = ff2(w.y, a.y, ac0); }
                { const ulonglong2 w = *(const ulonglong2*)(sm + M_WFRQ + ((q + 1) * 64 + fE) * 4);
                  const ulonglong2 a = *(const ulonglong2*)(xr + 4 * (q + 1));
                  ac1 = ff2(w.x, a.x, ac1); ac1 = ff2(w.y, a.y, ac1); }
            }
            float l0, h0, l1, h1;
            up2(ac0, l0, h0); up2(ac1, l1, h1);
            const float zh = sm[M_BFR + fE] + (l0 + h0) + (l1 + h1);
            const float ch = cbeta * zh + (1.f - cbeta) * xh;
            const float cc = cm * cx + (1.f - cm) * ch;
            sm[M_CLC + rE * 64 + fE] = cc;
            out[((size_t)(b0 + rE) * Sdim + s) * Fdim + fE] = cc;
            const float d1 = cx - xh, d2 = cx - zh, d3 = cx - ch;
            loss += cm * (d1 * d1 + d2 * d2 + d3 * d3) * cInv;
        }
        __syncthreads();

        // F: gates = gml + clc @ WihClc^T + h @ Whh^T
        {
            u64 A00 = 0ULL, A01 = 0ULL, A10 = 0ULL, A11 = 0ULL;
#pragma unroll
            for (int q = 0; q < 16; ++q)
                FS2(sm + M_WIHQ + (q * 512 + j0) * 4,
                    sm + M_WIHQ + (q * 512 + j1) * 4,
                    sm + M_CLC + 4 * q, 64);
#pragma unroll
            for (int q = 0; q < 4; ++q)
                FS2(sm + M_WHHR + (q * 512 + j0) * 4,
                    sm + M_WHHR + (q * 512 + j1) * 4,
                    sm + M_HR + 4 * q, 128);
#pragma unroll
            for (int q = 0; q < NR; ++q) {
                const float* AP = sm + M_HR + 16 + 4 * q;
                { const ulonglong2 a_ = *(const ulonglong2*)(AP);
                  A00 = ff2(rw[4 * q], a_.x, A00); A00 = ff2(rw[4 * q + 1], a_.y, A00);
                  A10 = ff2(rw[4 * q + 2], a_.x, A10); A10 = ff2(rw[4 * q + 3], a_.y, A10); }
                { const ulonglong2 a_ = *(const ulonglong2*)(AP + 128);
                  A01 = ff2(rw[4 * q], a_.x, A01); A01 = ff2(rw[4 * q + 1], a_.y, A01);
                  A11 = ff2(rw[4 * q + 2], a_.x, A11); A11 = ff2(rw[4 * q + 3], a_.y, A11); }
            }
#pragma unroll 7
            for (int q = NR; q < KQ; ++q)
                FS2(g_WhhQ + ((size_t)q * 512 + j0) * 4,
                    g_WhhQ + ((size_t)q * 512 + j1) * 4,
                    sm + M_HR + 16 + 4 * q, 128);
            float lo, hi;
            up2(A00, lo, hi); sm[M_GT + 0 * 512 + j0] = lo + hi + cgml[0];
            up2(A01, lo, hi); sm[M_GT + 1 * 512 + j0] = lo + hi + cgml[1];
            up2(A10, lo, hi); sm[M_GT + 0 * 512 + j1] = lo + hi + cgml[2];
            up2(A11, lo, hi); sm[M_GT + 1 * 512 + j1] = lo + hi + cgml[3];
        }
        __syncthreads();

        // G: LSTM update + apply gamma_h(s+1)
        {
            const float* gg = sm + M_GT + rG * 512;
            const float iv = fsig(gg[jG]);
            const float fv = fsig(gg[128 + jG]);
            const float gv = ftanh(gg[256 + jG]);
            const float ov = fsig(gg[384 + jG]);
            c_reg = fv * c_reg + iv * gv;
            sm[M_HR + rG * 128 + jG] = ov * ftanh(c_reg) * ghv;
        }
        __syncthreads();

        cx = nx; cm = nm; cbeta = nbeta;
#pragma unroll
        for (int r = 0; r < 4; ++r) cgml[r] = ngml[r];
    }

    sm[M_RED + t] = loss;
    __syncthreads();
    for (int off = 128; off > 0; off >>= 1) { if (t < off) sm[M_RED + t] += sm[M_RED + t + off]; __syncthreads(); }
    if (t == 0) g_lossPartial[blockIdx.x] = sm[M_RED];
}

__global__ void rits_loss_final(float* __restrict__ out, int out_size) {
    __shared__ float red[NBLK];
    const int t = threadIdx.x;
    red[t] = g_lossPartial[t];
    __syncthreads();
    for (int off = NBLK / 2; off > 0; off >>= 1) { if (t < off) red[t] += red[t + off]; __syncthreads(); }
    const long long bsf = (long long)Bdim * Sdim * Fdim;
    if (t == 0 && (long long)out_size > bsf) out[bsf] = red[0] / (float)Sdim;
}

extern "C" void kernel_launch(void* const* d_in, const int* in_sizes, int n_in,
                              void* d_out, int out_size) {
    const float* x   = (const float*)d_in[0];
    const float* m   = (const float*)d_in[1];
    const float* tt  = (const float*)d_in[2];
    const float* Wdh = (const float*)d_in[3];
    const float* bdh = (const float*)d_in[4];
    const float* Wdm = (const float*)d_in[5];
    const float* bdm = (const float*)d_in[6];
    const float* Wtr = (const float*)d_in[7];
    const float* btr = (const float*)d_in[8];
    const float* Wfr = (const float*)d_in[9];
    const float* bfr = (const float*)d_in[10];
    const float* Wwc = (const float*)d_in[11];
    const float* bwc = (const float*)d_in[12];
    const float* Wih = (const float*)d_in[13];
    const float* Whh = (const float*)d_in[14];
    const float* bih = (const float*)d_in[15];
    const float* bhh = (const float*)d_in[16];
    float* out = (float*)d_out;

    cudaFuncSetAttribute(rits_main, cudaFuncAttributeMaxDynamicSharedMemorySize, M_SMB);

    rits_pre<<<736, 256>>>(m, Whh);
    rits_main<<<NBLK, 256, M_SMB>>>(x, m, tt, Wdh, bdh, Wdm, bdm, Wtr, btr,
                                    Wfr, bfr, Wwc, bwc, Wih, Whh, bih, bhh, out);
    rits_loss_final<<<1, NBLK>>>(out, out_size);
}